// round 4
// baseline (speedup 1.0000x reference)
#include <cuda_runtime.h>
#include <cuda_bf16.h>
#include <cstdint>

#define N_MAX 8192
#define M_MAX 8192
#define D_FIX 256
#define EPSF 1e-12f

// ---------------- scratch (static device arrays; no runtime allocation) ----
__device__ float g_sim[(size_t)N_MAX * (size_t)M_MAX];    // 256 MB
__device__ float g_x2[N_MAX], g_xn2[M_MAX];
__device__ float g_k[N_MAX], g_t[N_MAX];
__device__ float g_rmin[N_MAX], g_rmax[N_MAX];

// ---------------- prep: row norms + sigmoid head ----------------------------
__global__ void prep_x_kernel(const float* __restrict__ x,
                              const float* __restrict__ W,
                              const float* __restrict__ b, int N) {
    int row  = blockIdx.x * 8 + (threadIdx.x >> 5);
    int lane = threadIdx.x & 31;
    if (row >= N) return;
    const float* xr = x + (size_t)row * D_FIX;
    float s2 = 0.f, p0 = 0.f, p1 = 0.f;
#pragma unroll
    for (int c = lane * 4; c < D_FIX; c += 128) {
        float4 v = *(const float4*)(xr + c);
        s2 += v.x * v.x + v.y * v.y + v.z * v.z + v.w * v.w;
        p0 += v.x * W[2*c + 0] + v.y * W[2*c + 2] + v.z * W[2*c + 4] + v.w * W[2*c + 6];
        p1 += v.x * W[2*c + 1] + v.y * W[2*c + 3] + v.z * W[2*c + 5] + v.w * W[2*c + 7];
    }
#pragma unroll
    for (int off = 16; off; off >>= 1) {
        s2 += __shfl_xor_sync(0xffffffffu, s2, off);
        p0 += __shfl_xor_sync(0xffffffffu, p0, off);
        p1 += __shfl_xor_sync(0xffffffffu, p1, off);
    }
    if (lane == 0) {
        g_x2[row] = s2;
        float kk = 1.f / (1.f + expf(-(p0 + b[0])));
        float tt = 1.f / (1.f + expf(-(p1 + b[1])));
        g_k[row] = fminf(fmaxf(kk, EPSF), 1.f - EPSF);
        g_t[row] = fminf(fmaxf(tt, EPSF), 1.f - EPSF);
    }
}

__global__ void prep_xn_kernel(const float* __restrict__ xn, int M) {
    int row  = blockIdx.x * 8 + (threadIdx.x >> 5);
    int lane = threadIdx.x & 31;
    if (row >= M) return;
    const float* xr = xn + (size_t)row * D_FIX;
    float s2 = 0.f;
#pragma unroll
    for (int c = lane * 4; c < D_FIX; c += 128) {
        float4 v = *(const float4*)(xr + c);
        s2 += v.x * v.x + v.y * v.y + v.z * v.z + v.w * v.w;
    }
#pragma unroll
    for (int off = 16; off; off >>= 1)
        s2 += __shfl_xor_sync(0xffffffffu, s2, off);
    if (lane == 0) g_xn2[row] = s2;
}

// ---------------- exact fp32 SIMT GEMM + sim epilogue -----------------------
// CTA 128x128, BK=16, 256 threads, 8x8 register tile per thread.
#define BM 128
#define BN 128
#define BK 16

__global__ void __launch_bounds__(256, 2) gemm_sim_f32_kernel(
        const float* __restrict__ x, const float* __restrict__ xn, int M) {
    __shared__ float As[BK][BM];
    __shared__ float Bs[BK][BN];

    const int tid = threadIdx.x;
    const int rowbase = blockIdx.y * BM;
    const int colbase = blockIdx.x * BN;
    const int tm = (tid >> 4) * 8;     // 0..120
    const int tn = (tid & 15) * 8;     // 0..120

    const int lm = tid & 127;          // load row within tile
    const int kq = tid >> 7;           // 0..1 -> k-halves

    float c[8][8];
#pragma unroll
    for (int i = 0; i < 8; i++)
#pragma unroll
        for (int j = 0; j < 8; j++) c[i][j] = 0.f;

    const float* arow = x  + (size_t)(rowbase + lm) * D_FIX + kq * 8;
    const float* brow = xn + (size_t)(colbase + lm) * D_FIX + kq * 8;

#pragma unroll 1
    for (int k0 = 0; k0 < D_FIX; k0 += BK) {
#pragma unroll
        for (int it = 0; it < 2; it++) {
            float4 va = *(const float4*)(arow + k0 + it * 4);
            float4 vb = *(const float4*)(brow + k0 + it * 4);
            int kb = kq * 8 + it * 4;
            As[kb + 0][lm] = va.x; As[kb + 1][lm] = va.y;
            As[kb + 2][lm] = va.z; As[kb + 3][lm] = va.w;
            Bs[kb + 0][lm] = vb.x; Bs[kb + 1][lm] = vb.y;
            Bs[kb + 2][lm] = vb.z; Bs[kb + 3][lm] = vb.w;
        }
        __syncthreads();
#pragma unroll
        for (int kk = 0; kk < BK; kk++) {
            float4 a0 = *(const float4*)&As[kk][tm];
            float4 a1 = *(const float4*)&As[kk][tm + 4];
            float4 b0 = *(const float4*)&Bs[kk][tn];
            float4 b1 = *(const float4*)&Bs[kk][tn + 4];
            float av[8] = {a0.x, a0.y, a0.z, a0.w, a1.x, a1.y, a1.z, a1.w};
            float bv[8] = {b0.x, b0.y, b0.z, b0.w, b1.x, b1.y, b1.z, b1.w};
#pragma unroll
            for (int i = 0; i < 8; i++)
#pragma unroll
                for (int j = 0; j < 8; j++) c[i][j] += av[i] * bv[j];
        }
        __syncthreads();
    }

    // epilogue: d2 = x2 + xn2 - 2*dot ; sim = -sqrt(max(d2,0)) -> scratch
    float yn[8];
#pragma unroll
    for (int j = 0; j < 8; j++) yn[j] = g_xn2[colbase + tn + j];
#pragma unroll
    for (int i = 0; i < 8; i++) {
        int row = rowbase + tm + i;
        float xa = g_x2[row];
        float o[8];
#pragma unroll
        for (int j = 0; j < 8; j++)
            o[j] = -sqrtf(fmaxf(xa + yn[j] - 2.f * c[i][j], 0.f));
        *(float4*)(g_sim + (size_t)row * M + colbase + tn)     = make_float4(o[0], o[1], o[2], o[3]);
        *(float4*)(g_sim + (size_t)row * M + colbase + tn + 4) = make_float4(o[4], o[5], o[6], o[7]);
    }
}

// ---------------- per-row min/max over scratch ------------------------------
__global__ void rowminmax_kernel(int M) {
    int row = blockIdx.x;
    const float4* p = (const float4*)(g_sim + (size_t)row * M);
    int n4 = M >> 2;
    float mn = 3.4e38f, mx = -3.4e38f;
    for (int i = threadIdx.x; i < n4; i += blockDim.x) {
        float4 v = p[i];
        mn = fminf(mn, fminf(fminf(v.x, v.y), fminf(v.z, v.w)));
        mx = fmaxf(mx, fmaxf(fmaxf(v.x, v.y), fmaxf(v.z, v.w)));
    }
#pragma unroll
    for (int off = 16; off; off >>= 1) {
        mn = fminf(mn, __shfl_xor_sync(0xffffffffu, mn, off));
        mx = fmaxf(mx, __shfl_xor_sync(0xffffffffu, mx, off));
    }
    __shared__ float smn[8], smx[8];
    int lane = threadIdx.x & 31, warp = threadIdx.x >> 5;
    if (lane == 0) { smn[warp] = mn; smx[warp] = mx; }
    __syncthreads();
    if (threadIdx.x == 0) {
        float a = smn[0], b2 = smx[0];
#pragma unroll
        for (int w = 1; w < 8; w++) { a = fminf(a, smn[w]); b2 = fmaxf(b2, smx[w]); }
        g_rmin[row] = a;
        g_rmax[row] = b2;
    }
}

// ---------------- normalize + soft-KNN shift -------------------------------
__device__ __forceinline__ float sknn(float v, float mn, float inv,
                                      float k, float alpha) {
    float s = fmaxf((v - mn) * inv, EPSF);
    float sh = alpha * (k - s) * logf(s / k);
    return s + ((s <= k) ? sh : 0.f);
}

__global__ void epilogue_kernel(float* __restrict__ out, int M) {
    int row = blockIdx.y;
    int c = (blockIdx.x * blockDim.x + threadIdx.x) * 4;
    if (c >= M) return;
    float k  = g_k[row];
    float t  = g_t[row];
    float mn = g_rmin[row];
    float inv = 1.f / (g_rmax[row] - mn);
    float alpha = t / (1.f - t);
    float4 v = *(const float4*)(g_sim + (size_t)row * M + c);
    float4 o;
    o.x = sknn(v.x, mn, inv, k, alpha);
    o.y = sknn(v.y, mn, inv, k, alpha);
    o.z = sknn(v.z, mn, inv, k, alpha);
    o.w = sknn(v.w, mn, inv, k, alpha);
    *(float4*)(out + (size_t)row * M + c) = o;
}

// ---------------- launcher ---------------------------------------------------
extern "C" void kernel_launch(void* const* d_in, const int* in_sizes, int n_in,
                              void* d_out, int out_size) {
    const float* x  = (const float*)d_in[0];
    const float* xn = (const float*)d_in[1];
    const float* W  = (const float*)d_in[2];
    const float* b  = (const float*)d_in[3];
    float* out = (float*)d_out;

    int D = in_sizes[2] / 2;            // 256
    int N = in_sizes[0] / D;            // 8192
    int M = in_sizes[1] / D;            // 8192

    prep_x_kernel <<<(N + 7) / 8, 256>>>(x, W, b, N);
    prep_xn_kernel<<<(M + 7) / 8, 256>>>(xn, M);

    dim3 gg(M / BN, N / BM);
    gemm_sim_f32_kernel<<<gg, 256>>>(x, xn, M);

    rowminmax_kernel<<<N, 256>>>(M);

    dim3 ge((M / 4 + 255) / 256, N);
    epilogue_kernel<<<ge, 256>>>(out, M);
}

// round 5
// speedup vs baseline: 1.0806x; 1.0806x over previous
#include <cuda_runtime.h>
#include <cuda_bf16.h>
#include <cstdint>

#define N_MAX 8192
#define M_MAX 8192
#define D_FIX 256
#define EPSF 1e-12f

// ---------------- scratch (static device arrays; no runtime allocation) ----
__device__ float g_sim[(size_t)N_MAX * (size_t)M_MAX];    // 256 MB
__device__ float g_x2[N_MAX], g_xn2[M_MAX];
__device__ float g_k[N_MAX], g_t[N_MAX];
__device__ unsigned int g_rminu[N_MAX], g_rmaxu[N_MAX];   // flipped-uint min/max

// monotone float->uint key: uint compare == float compare
__device__ __forceinline__ unsigned int fkey(float f) {
    unsigned int b = __float_as_uint(f);
    return (b & 0x80000000u) ? ~b : (b | 0x80000000u);
}
__device__ __forceinline__ float funkey(unsigned int u) {
    return __uint_as_float((u & 0x80000000u) ? (u & 0x7FFFFFFFu) : ~u);
}

// ---------------- init atomic identities ------------------------------------
__global__ void init_minmax_kernel(int N) {
    int i = blockIdx.x * blockDim.x + threadIdx.x;
    if (i < N) { g_rminu[i] = 0xFFFFFFFFu; g_rmaxu[i] = 0u; }
}

// ---------------- prep: row norms + sigmoid head ----------------------------
__global__ void prep_x_kernel(const float* __restrict__ x,
                              const float* __restrict__ W,
                              const float* __restrict__ b, int N) {
    int row  = blockIdx.x * 8 + (threadIdx.x >> 5);
    int lane = threadIdx.x & 31;
    if (row >= N) return;
    const float* xr = x + (size_t)row * D_FIX;
    float s2 = 0.f, p0 = 0.f, p1 = 0.f;
#pragma unroll
    for (int c = lane * 4; c < D_FIX; c += 128) {
        float4 v = *(const float4*)(xr + c);
        s2 += v.x * v.x + v.y * v.y + v.z * v.z + v.w * v.w;
        p0 += v.x * W[2*c + 0] + v.y * W[2*c + 2] + v.z * W[2*c + 4] + v.w * W[2*c + 6];
        p1 += v.x * W[2*c + 1] + v.y * W[2*c + 3] + v.z * W[2*c + 5] + v.w * W[2*c + 7];
    }
#pragma unroll
    for (int off = 16; off; off >>= 1) {
        s2 += __shfl_xor_sync(0xffffffffu, s2, off);
        p0 += __shfl_xor_sync(0xffffffffu, p0, off);
        p1 += __shfl_xor_sync(0xffffffffu, p1, off);
    }
    if (lane == 0) {
        g_x2[row] = s2;
        float kk = 1.f / (1.f + expf(-(p0 + b[0])));
        float tt = 1.f / (1.f + expf(-(p1 + b[1])));
        g_k[row] = fminf(fmaxf(kk, EPSF), 1.f - EPSF);
        g_t[row] = fminf(fmaxf(tt, EPSF), 1.f - EPSF);
    }
}

__global__ void prep_xn_kernel(const float* __restrict__ xn, int M) {
    int row  = blockIdx.x * 8 + (threadIdx.x >> 5);
    int lane = threadIdx.x & 31;
    if (row >= M) return;
    const float* xr = xn + (size_t)row * D_FIX;
    float s2 = 0.f;
#pragma unroll
    for (int c = lane * 4; c < D_FIX; c += 128) {
        float4 v = *(const float4*)(xr + c);
        s2 += v.x * v.x + v.y * v.y + v.z * v.z + v.w * v.w;
    }
#pragma unroll
    for (int off = 16; off; off >>= 1)
        s2 += __shfl_xor_sync(0xffffffffu, s2, off);
    if (lane == 0) g_xn2[row] = s2;
}

// ---------------- fp32x2 SIMT GEMM + sim epilogue + fused min/max -----------
// CTA 128x128, BK=16, 256 threads, 8x8 register tile per thread.
// Math via fma.rn.f32x2 (packed dual fp32 FMA) - bitwise identical to scalar.
#define BM 128
#define BN 128
#define BK 16

__device__ __forceinline__ unsigned long long pack2(float lo, float hi) {
    unsigned long long r;
    asm("mov.b64 %0, {%1, %2};" : "=l"(r) : "f"(lo), "f"(hi));
    return r;
}
__device__ __forceinline__ void unpack2(float& lo, float& hi, unsigned long long v) {
    asm("mov.b64 {%0, %1}, %2;" : "=f"(lo), "=f"(hi) : "l"(v));
}
__device__ __forceinline__ void fma2(unsigned long long& acc,
                                     unsigned long long a, unsigned long long b) {
    asm("fma.rn.f32x2 %0, %1, %2, %0;" : "+l"(acc) : "l"(a), "l"(b));
}

__global__ void __launch_bounds__(256, 2) gemm_sim_f32_kernel(
        const float* __restrict__ x, const float* __restrict__ xn, int M) {
    __shared__ float As[BK][BM];
    __shared__ float Bs[BK][BN];

    const int tid = threadIdx.x;
    const int rowbase = blockIdx.y * BM;
    const int colbase = blockIdx.x * BN;
    const int tm = (tid >> 4) * 8;     // 0..120
    const int tn = (tid & 15) * 8;     // 0..120

    const int lm = tid & 127;          // load row within tile
    const int kq = tid >> 7;           // 0..1 -> k-halves

    unsigned long long acc[8][4];      // [row][col-pair], packed f32x2
#pragma unroll
    for (int i = 0; i < 8; i++)
#pragma unroll
        for (int p = 0; p < 4; p++) acc[i][p] = 0ULL;

    const float* arow = x  + (size_t)(rowbase + lm) * D_FIX + kq * 8;
    const float* brow = xn + (size_t)(colbase + lm) * D_FIX + kq * 8;

#pragma unroll 1
    for (int k0 = 0; k0 < D_FIX; k0 += BK) {
#pragma unroll
        for (int it = 0; it < 2; it++) {
            float4 va = *(const float4*)(arow + k0 + it * 4);
            float4 vb = *(const float4*)(brow + k0 + it * 4);
            int kb = kq * 8 + it * 4;
            As[kb + 0][lm] = va.x; As[kb + 1][lm] = va.y;
            As[kb + 2][lm] = va.z; As[kb + 3][lm] = va.w;
            Bs[kb + 0][lm] = vb.x; Bs[kb + 1][lm] = vb.y;
            Bs[kb + 2][lm] = vb.z; Bs[kb + 3][lm] = vb.w;
        }
        __syncthreads();
#pragma unroll
        for (int kk = 0; kk < BK; kk++) {
            float4 a0 = *(const float4*)&As[kk][tm];
            float4 a1 = *(const float4*)&As[kk][tm + 4];
            float4 b0 = *(const float4*)&Bs[kk][tn];
            float4 b1 = *(const float4*)&Bs[kk][tn + 4];
            unsigned long long B0 = pack2(b0.x, b0.y);
            unsigned long long B1 = pack2(b0.z, b0.w);
            unsigned long long B2 = pack2(b1.x, b1.y);
            unsigned long long B3 = pack2(b1.z, b1.w);
            float av[8] = {a0.x, a0.y, a0.z, a0.w, a1.x, a1.y, a1.z, a1.w};
#pragma unroll
            for (int i = 0; i < 8; i++) {
                unsigned long long Ad = pack2(av[i], av[i]);
                fma2(acc[i][0], Ad, B0);
                fma2(acc[i][1], Ad, B1);
                fma2(acc[i][2], Ad, B2);
                fma2(acc[i][3], Ad, B3);
            }
        }
        __syncthreads();
    }

    // epilogue: d2 = x2 + xn2 - 2*dot ; sim = -sqrt(max(d2,0)) -> scratch
    // plus fused per-row min/max (flipped-uint atomics).
    float yn[8];
#pragma unroll
    for (int j = 0; j < 8; j++) yn[j] = g_xn2[colbase + tn + j];

    const int lane = tid & 31;
#pragma unroll
    for (int i = 0; i < 8; i++) {
        int row = rowbase + tm + i;
        float xa = g_x2[row];
        float o[8];
#pragma unroll
        for (int j = 0; j < 8; j++) {
            float c;
            { float locked_lo, locked_hi; unpack2(locked_lo, locked_hi, acc[i][j >> 1]);
              c = (j & 1) ? locked_hi : locked_lo; }
            o[j] = -sqrtf(fmaxf(xa + yn[j] - 2.f * c, 0.f));
        }
        *(float4*)(g_sim + (size_t)row * M + colbase + tn)     = make_float4(o[0], o[1], o[2], o[3]);
        *(float4*)(g_sim + (size_t)row * M + colbase + tn + 4) = make_float4(o[4], o[5], o[6], o[7]);

        // per-thread min/max over 8 cols
        float mn = o[0], mx = o[0];
#pragma unroll
        for (int j = 1; j < 8; j++) { mn = fminf(mn, o[j]); mx = fmaxf(mx, o[j]); }
        // reduce across the 16 threads sharing this row (same tid>>4 group,
        // which is a contiguous 16-lane half of a warp)
#pragma unroll
        for (int off = 8; off; off >>= 1) {
            mn = fminf(mn, __shfl_xor_sync(0xffffffffu, mn, off));
            mx = fmaxf(mx, __shfl_xor_sync(0xffffffffu, mx, off));
        }
        if ((lane & 15) == 0) {
            atomicMin(&g_rminu[row], fkey(mn));
            atomicMax(&g_rmaxu[row], fkey(mx));
        }
    }
}

// ---------------- normalize + soft-KNN shift -------------------------------
__device__ __forceinline__ float sknn(float v, float mn, float inv,
                                      float k, float alpha) {
    float s = fmaxf((v - mn) * inv, EPSF);
    float sh = alpha * (k - s) * logf(s / k);
    return s + ((s <= k) ? sh : 0.f);
}

__global__ void epilogue_kernel(float* __restrict__ out, int M) {
    int row = blockIdx.y;
    int c = (blockIdx.x * blockDim.x + threadIdx.x) * 4;
    if (c >= M) return;
    float k  = g_k[row];
    float t  = g_t[row];
    float mn = funkey(g_rminu[row]);
    float mx = funkey(g_rmaxu[row]);
    float inv = 1.f / (mx - mn);
    float alpha = t / (1.f - t);
    float4 v = *(const float4*)(g_sim + (size_t)row * M + c);
    float4 o;
    o.x = sknn(v.x, mn, inv, k, alpha);
    o.y = sknn(v.y, mn, inv, k, alpha);
    o.z = sknn(v.z, mn, inv, k, alpha);
    o.w = sknn(v.w, mn, inv, k, alpha);
    *(float4*)(out + (size_t)row * M + c) = o;
}

// ---------------- launcher ---------------------------------------------------
extern "C" void kernel_launch(void* const* d_in, const int* in_sizes, int n_in,
                              void* d_out, int out_size) {
    const float* x  = (const float*)d_in[0];
    const float* xn = (const float*)d_in[1];
    const float* W  = (const float*)d_in[2];
    const float* b  = (const float*)d_in[3];
    float* out = (float*)d_out;

    int D = in_sizes[2] / 2;            // 256
    int N = in_sizes[0] / D;            // 8192
    int M = in_sizes[1] / D;            // 8192

    init_minmax_kernel<<<(N + 255) / 256, 256>>>(N);
    prep_x_kernel <<<(N + 7) / 8, 256>>>(x, W, b, N);
    prep_xn_kernel<<<(M + 7) / 8, 256>>>(xn, M);

    dim3 gg(M / BN, N / BM);
    gemm_sim_f32_kernel<<<gg, 256>>>(x, xn, M);

    dim3 ge((M / 4 + 255) / 256, N);
    epilogue_kernel<<<ge, 256>>>(out, M);
}

// round 6
// speedup vs baseline: 1.3066x; 1.2091x over previous
#include <cuda_runtime.h>
#include <cuda_bf16.h>
#include <cstdint>

#define N_MAX 8192
#define M_MAX 8192
#define D_FIX 256
#define EPSF 1e-12f

// ---------------- scratch (static device arrays; no runtime allocation) ----
__device__ float g_sim[(size_t)N_MAX * (size_t)M_MAX];    // 256 MB
__device__ float g_x2[N_MAX], g_xn2[M_MAX];
__device__ float g_k[N_MAX], g_t[N_MAX];
__device__ unsigned int g_rminu[N_MAX], g_rmaxu[N_MAX];   // flipped-uint min/max

// monotone float->uint key: uint compare == float compare
__device__ __forceinline__ unsigned int fkey(float f) {
    unsigned int b = __float_as_uint(f);
    return (b & 0x80000000u) ? ~b : (b | 0x80000000u);
}
__device__ __forceinline__ float funkey(unsigned int u) {
    return __uint_as_float((u & 0x80000000u) ? (u & 0x7FFFFFFFu) : ~u);
}

// ---------------- init atomic identities ------------------------------------
__global__ void init_minmax_kernel(int N) {
    int i = blockIdx.x * blockDim.x + threadIdx.x;
    if (i < N) { g_rminu[i] = 0xFFFFFFFFu; g_rmaxu[i] = 0u; }
}

// ---------------- prep: row norms + sigmoid head ----------------------------
__global__ void prep_x_kernel(const float* __restrict__ x,
                              const float* __restrict__ W,
                              const float* __restrict__ b, int N) {
    int row  = blockIdx.x * 8 + (threadIdx.x >> 5);
    int lane = threadIdx.x & 31;
    if (row >= N) return;
    const float* xr = x + (size_t)row * D_FIX;
    float s2 = 0.f, p0 = 0.f, p1 = 0.f;
#pragma unroll
    for (int c = lane * 4; c < D_FIX; c += 128) {
        float4 v = *(const float4*)(xr + c);
        s2 += v.x * v.x + v.y * v.y + v.z * v.z + v.w * v.w;
        p0 += v.x * W[2*c + 0] + v.y * W[2*c + 2] + v.z * W[2*c + 4] + v.w * W[2*c + 6];
        p1 += v.x * W[2*c + 1] + v.y * W[2*c + 3] + v.z * W[2*c + 5] + v.w * W[2*c + 7];
    }
#pragma unroll
    for (int off = 16; off; off >>= 1) {
        s2 += __shfl_xor_sync(0xffffffffu, s2, off);
        p0 += __shfl_xor_sync(0xffffffffu, p0, off);
        p1 += __shfl_xor_sync(0xffffffffu, p1, off);
    }
    if (lane == 0) {
        g_x2[row] = s2;
        float kk = 1.f / (1.f + expf(-(p0 + b[0])));
        float tt = 1.f / (1.f + expf(-(p1 + b[1])));
        g_k[row] = fminf(fmaxf(kk, EPSF), 1.f - EPSF);
        g_t[row] = fminf(fmaxf(tt, EPSF), 1.f - EPSF);
    }
}

__global__ void prep_xn_kernel(const float* __restrict__ xn, int M) {
    int row  = blockIdx.x * 8 + (threadIdx.x >> 5);
    int lane = threadIdx.x & 31;
    if (row >= M) return;
    const float* xr = xn + (size_t)row * D_FIX;
    float s2 = 0.f;
#pragma unroll
    for (int c = lane * 4; c < D_FIX; c += 128) {
        float4 v = *(const float4*)(xr + c);
        s2 += v.x * v.x + v.y * v.y + v.z * v.z + v.w * v.w;
    }
#pragma unroll
    for (int off = 16; off; off >>= 1)
        s2 += __shfl_xor_sync(0xffffffffu, s2, off);
    if (lane == 0) g_xn2[row] = s2;
}

// ---------------- fp32x2 SIMT GEMM + sim epilogue + fused min/max -----------
// CTA 128x128, BK=16, 256 threads, 8x8 per-thread tile.
// Per-thread cols = {4j..4j+3} u {64+4j..64+4j+3}  (bank-conflict-free LDS.128)
// Math via fma.rn.f32x2 - bitwise identical to scalar fp32.
#define BM 128
#define BN 128
#define BK 16

__device__ __forceinline__ unsigned long long pack2(float lo, float hi) {
    unsigned long long r;
    asm("mov.b64 %0, {%1, %2};" : "=l"(r) : "f"(lo), "f"(hi));
    return r;
}
__device__ __forceinline__ void unpack2(float& lo, float& hi, unsigned long long v) {
    asm("mov.b64 {%0, %1}, %2;" : "=f"(lo), "=f"(hi) : "l"(v));
}
__device__ __forceinline__ void fma2(unsigned long long& acc,
                                     unsigned long long a, unsigned long long b) {
    asm("fma.rn.f32x2 %0, %1, %2, %0;" : "+l"(acc) : "l"(a), "l"(b));
}

__global__ void __launch_bounds__(256, 2) gemm_sim_f32_kernel(
        const float* __restrict__ x, const float* __restrict__ xn, int M) {
    __shared__ float As[BK][BM];
    __shared__ float Bs[BK][BN];

    const int tid = threadIdx.x;
    const int rowbase = blockIdx.y * BM;
    const int colbase = blockIdx.x * BN;
    const int tm = (tid >> 4) * 8;     // 8 consecutive rows
    const int tn = (tid & 15) * 4;     // cols tn..tn+3 and 64+tn..64+tn+3

    const int lm = tid & 127;          // load row within tile
    const int kq = tid >> 7;           // 0..1 -> k-halves

    unsigned long long acc[8][4];      // [row][colpair]: p0,p1 = lo group, p2,p3 = hi group
#pragma unroll
    for (int i = 0; i < 8; i++)
#pragma unroll
        for (int p = 0; p < 4; p++) acc[i][p] = 0ULL;

    const float* arow = x  + (size_t)(rowbase + lm) * D_FIX + kq * 8;
    const float* brow = xn + (size_t)(colbase + lm) * D_FIX + kq * 8;

    // prefetch chunk 0
    float4 va0 = *(const float4*)(arow + 0);
    float4 va1 = *(const float4*)(arow + 4);
    float4 vb0 = *(const float4*)(brow + 0);
    float4 vb1 = *(const float4*)(brow + 4);

#pragma unroll 1
    for (int k0 = 0; k0 < D_FIX; k0 += BK) {
        // store prefetched chunk to smem
        {
            int kb = kq * 8;
            As[kb + 0][lm] = va0.x; As[kb + 1][lm] = va0.y;
            As[kb + 2][lm] = va0.z; As[kb + 3][lm] = va0.w;
            As[kb + 4][lm] = va1.x; As[kb + 5][lm] = va1.y;
            As[kb + 6][lm] = va1.z; As[kb + 7][lm] = va1.w;
            Bs[kb + 0][lm] = vb0.x; Bs[kb + 1][lm] = vb0.y;
            Bs[kb + 2][lm] = vb0.z; Bs[kb + 3][lm] = vb0.w;
            Bs[kb + 4][lm] = vb1.x; Bs[kb + 5][lm] = vb1.y;
            Bs[kb + 6][lm] = vb1.z; Bs[kb + 7][lm] = vb1.w;
        }
        __syncthreads();

        // prefetch next chunk (overlaps with compute below)
        if (k0 + BK < D_FIX) {
            va0 = *(const float4*)(arow + k0 + BK + 0);
            va1 = *(const float4*)(arow + k0 + BK + 4);
            vb0 = *(const float4*)(brow + k0 + BK + 0);
            vb1 = *(const float4*)(brow + k0 + BK + 4);
        }

#pragma unroll
        for (int kk = 0; kk < BK; kk++) {
            float4 a0 = *(const float4*)&As[kk][tm];
            float4 a1 = *(const float4*)&As[kk][tm + 4];
            float4 b0 = *(const float4*)&Bs[kk][tn];        // conflict-free
            float4 b1 = *(const float4*)&Bs[kk][tn + 64];   // conflict-free
            unsigned long long B0 = pack2(b0.x, b0.y);
            unsigned long long B1 = pack2(b0.z, b0.w);
            unsigned long long B2 = pack2(b1.x, b1.y);
            unsigned long long B3 = pack2(b1.z, b1.w);
            float av[8] = {a0.x, a0.y, a0.z, a0.w, a1.x, a1.y, a1.z, a1.w};
#pragma unroll
            for (int i = 0; i < 8; i++) {
                unsigned long long Ad = pack2(av[i], av[i]);
                fma2(acc[i][0], Ad, B0);
                fma2(acc[i][1], Ad, B1);
                fma2(acc[i][2], Ad, B2);
                fma2(acc[i][3], Ad, B3);
            }
        }
        __syncthreads();
    }

    // epilogue: d2 = x2 + xn2 - 2*dot ; sim = -sqrt(max(d2,0)) -> scratch
    // plus fused per-row min/max (flipped-uint atomics).
    float yn[8];
#pragma unroll
    for (int j = 0; j < 4; j++) {
        yn[j]     = g_xn2[colbase + tn + j];
        yn[4 + j] = g_xn2[colbase + 64 + tn + j];
    }

    const int lane = tid & 31;
#pragma unroll
    for (int i = 0; i < 8; i++) {
        int row = rowbase + tm + i;
        float xa = g_x2[row];
        float o[8];
#pragma unroll
        for (int j = 0; j < 8; j++) {
            float c;
            { float lo, hi; unpack2(lo, hi, acc[i][j >> 1]);
              c = (j & 1) ? hi : lo; }
            o[j] = -sqrtf(fmaxf(xa + yn[j] - 2.f * c, 0.f));
        }
        *(float4*)(g_sim + (size_t)row * M + colbase + tn)      = make_float4(o[0], o[1], o[2], o[3]);
        *(float4*)(g_sim + (size_t)row * M + colbase + 64 + tn) = make_float4(o[4], o[5], o[6], o[7]);

        float mn = o[0], mx = o[0];
#pragma unroll
        for (int j = 1; j < 8; j++) { mn = fminf(mn, o[j]); mx = fmaxf(mx, o[j]); }
        // reduce across the 16 threads sharing this row (contiguous half-warp)
#pragma unroll
        for (int off = 8; off; off >>= 1) {
            mn = fminf(mn, __shfl_xor_sync(0xffffffffu, mn, off));
            mx = fmaxf(mx, __shfl_xor_sync(0xffffffffu, mx, off));
        }
        if ((lane & 15) == 0) {
            atomicMin(&g_rminu[row], fkey(mn));
            atomicMax(&g_rmaxu[row], fkey(mx));
        }
    }
}

// ---------------- normalize + soft-KNN shift -------------------------------
__device__ __forceinline__ float sknn(float v, float mn, float inv,
                                      float k, float alpha) {
    float s = fmaxf((v - mn) * inv, EPSF);
    float sh = alpha * (k - s) * logf(s / k);
    return s + ((s <= k) ? sh : 0.f);
}

__global__ void epilogue_kernel(float* __restrict__ out, int M) {
    int row = blockIdx.y;
    int c = (blockIdx.x * blockDim.x + threadIdx.x) * 4;
    if (c >= M) return;
    float k  = g_k[row];
    float t  = g_t[row];
    float mn = funkey(g_rminu[row]);
    float mx = funkey(g_rmaxu[row]);
    float inv = 1.f / (mx - mn);
    float alpha = t / (1.f - t);
    float4 v = *(const float4*)(g_sim + (size_t)row * M + c);
    float4 o;
    o.x = sknn(v.x, mn, inv, k, alpha);
    o.y = sknn(v.y, mn, inv, k, alpha);
    o.z = sknn(v.z, mn, inv, k, alpha);
    o.w = sknn(v.w, mn, inv, k, alpha);
    *(float4*)(out + (size_t)row * M + c) = o;
}

// ---------------- launcher ---------------------------------------------------
extern "C" void kernel_launch(void* const* d_in, const int* in_sizes, int n_in,
                              void* d_out, int out_size) {
    const float* x  = (const float*)d_in[0];
    const float* xn = (const float*)d_in[1];
    const float* W  = (const float*)d_in[2];
    const float* b  = (const float*)d_in[3];
    float* out = (float*)d_out;

    int D = in_sizes[2] / 2;            // 256
    int N = in_sizes[0] / D;            // 8192
    int M = in_sizes[1] / D;            // 8192

    init_minmax_kernel<<<(N + 255) / 256, 256>>>(N);
    prep_x_kernel <<<(N + 7) / 8, 256>>>(x, W, b, N);
    prep_xn_kernel<<<(M + 7) / 8, 256>>>(xn, M);

    dim3 gg(M / BN, N / BM);
    gemm_sim_f32_kernel<<<gg, 256>>>(x, xn, M);

    dim3 ge((M / 4 + 255) / 256, N);
    epilogue_kernel<<<ge, 256>>>(out, M);
}

// round 8
// speedup vs baseline: 1.9018x; 1.4555x over previous
#include <cuda_runtime.h>
#include <cuda_fp16.h>
#include <cstdint>

#define NROWS 8192
#define D_FIX 256
#define KEXT  768             // 3 segments of 256: hh, hm, mh
#define EPSF  1e-12f

// ---------------- scratch (static device arrays; no runtime allocation) ----
__device__ float g_sim[(size_t)NROWS * (size_t)NROWS];          // 256 MB
__device__ __align__(16) __half g_xa[(size_t)NROWS * KEXT];     // 12.6 MB
__device__ __align__(16) __half g_xb[(size_t)NROWS * KEXT];     // 12.6 MB
__device__ float g_x2[NROWS], g_xn2[NROWS];
__device__ float g_k[NROWS], g_t[NROWS];
__device__ unsigned int g_rminu[NROWS], g_rmaxu[NROWS];

// monotone float<->uint key
__device__ __forceinline__ unsigned int fkey(float f) {
    unsigned int b = __float_as_uint(f);
    return (b & 0x80000000u) ? ~b : (b | 0x80000000u);
}
__device__ __forceinline__ float funkey(unsigned int u) {
    return __uint_as_float((u & 0x80000000u) ? (u & 0x7FFFFFFFu) : ~u);
}

__global__ void init_minmax_kernel(int N) {
    int i = blockIdx.x * blockDim.x + threadIdx.x;
    if (i < N) { g_rminu[i] = 0xFFFFFFFFu; g_rmaxu[i] = 0u; }
}

// ---------------- prep: fp16 2-way split + row norms + sigmoid head --------
// A segments: [h | h | m],  B segments: [h | m | h]
__global__ void prep_x_kernel(const float* __restrict__ x,
                              const float* __restrict__ W,
                              const float* __restrict__ b, int N) {
    int row  = blockIdx.x * 8 + (threadIdx.x >> 5);
    int lane = threadIdx.x & 31;
    if (row >= N) return;
    const float* xr = x + (size_t)row * D_FIX;
    float s2 = 0.f, p0 = 0.f, p1 = 0.f;
#pragma unroll
    for (int c = lane * 4; c < D_FIX; c += 128) {
        float4 v = *(const float4*)(xr + c);
        s2 += v.x * v.x + v.y * v.y + v.z * v.z + v.w * v.w;
        p0 += v.x * W[2*c + 0] + v.y * W[2*c + 2] + v.z * W[2*c + 4] + v.w * W[2*c + 6];
        p1 += v.x * W[2*c + 1] + v.y * W[2*c + 3] + v.z * W[2*c + 5] + v.w * W[2*c + 7];
        float f[4] = {v.x, v.y, v.z, v.w};
        size_t o = (size_t)row * KEXT + c;
#pragma unroll
        for (int q = 0; q < 4; q++) {
            __half h = __float2half_rn(f[q]);
            __half m = __float2half_rn(f[q] - __half2float(h));
            g_xa[o + q]       = h;
            g_xa[o + q + 256] = h;
            g_xa[o + q + 512] = m;
        }
    }
#pragma unroll
    for (int off = 16; off; off >>= 1) {
        s2 += __shfl_xor_sync(0xffffffffu, s2, off);
        p0 += __shfl_xor_sync(0xffffffffu, p0, off);
        p1 += __shfl_xor_sync(0xffffffffu, p1, off);
    }
    if (lane == 0) {
        g_x2[row] = s2;
        float kk = 1.f / (1.f + expf(-(p0 + b[0])));
        float tt = 1.f / (1.f + expf(-(p1 + b[1])));
        g_k[row] = fminf(fmaxf(kk, EPSF), 1.f - EPSF);
        g_t[row] = fminf(fmaxf(tt, EPSF), 1.f - EPSF);
    }
}

__global__ void prep_xn_kernel(const float* __restrict__ xn, int M) {
    int row  = blockIdx.x * 8 + (threadIdx.x >> 5);
    int lane = threadIdx.x & 31;
    if (row >= M) return;
    const float* xr = xn + (size_t)row * D_FIX;
    float s2 = 0.f;
#pragma unroll
    for (int c = lane * 4; c < D_FIX; c += 128) {
        float4 v = *(const float4*)(xr + c);
        s2 += v.x * v.x + v.y * v.y + v.z * v.z + v.w * v.w;
        float f[4] = {v.x, v.y, v.z, v.w};
        size_t o = (size_t)row * KEXT + c;
#pragma unroll
        for (int q = 0; q < 4; q++) {
            __half h = __float2half_rn(f[q]);
            __half m = __float2half_rn(f[q] - __half2float(h));
            g_xb[o + q]       = h;
            g_xb[o + q + 256] = m;
            g_xb[o + q + 512] = h;
        }
    }
#pragma unroll
    for (int off = 16; off; off >>= 1)
        s2 += __shfl_xor_sync(0xffffffffu, s2, off);
    if (lane == 0) g_xn2[row] = s2;
}

// ---------------- fp16 mma.sync GEMM + sim epilogue + fused min/max --------
// CTA tile 128x128, K=768 in 12 chunks of 64. 8 warps: 4(m) x 2(n),
// each warp 32x64 via mma.sync.m16n8k16 f16. Smem stride 72 halfs.
#define BM 128
#define BN 128
#define BK 64
#define SST 72

__device__ __forceinline__ void ldsm_x4(uint32_t* r, uint32_t addr) {
    asm volatile("ldmatrix.sync.aligned.m8n8.x4.shared.b16 {%0,%1,%2,%3}, [%4];"
                 : "=r"(r[0]), "=r"(r[1]), "=r"(r[2]), "=r"(r[3]) : "r"(addr));
}

__device__ __forceinline__ void mma_f16(float* c, const uint32_t* a,
                                        uint32_t b0, uint32_t b1) {
    asm volatile(
        "mma.sync.aligned.m16n8k16.row.col.f32.f16.f16.f32 "
        "{%0,%1,%2,%3}, {%4,%5,%6,%7}, {%8,%9}, {%0,%1,%2,%3};"
        : "+f"(c[0]), "+f"(c[1]), "+f"(c[2]), "+f"(c[3])
        : "r"(a[0]), "r"(a[1]), "r"(a[2]), "r"(a[3]), "r"(b0), "r"(b1));
}

__global__ void __launch_bounds__(256, 1) gemm_sim_kernel(int M) {
    __shared__ __align__(16) __half As[BM][SST];
    __shared__ __align__(16) __half Bs[BN][SST];

    const int tid  = threadIdx.x;
    const int lane = tid & 31;
    const int warp = tid >> 5;
    const int wm   = warp >> 1;   // 0..3
    const int wn   = warp & 1;    // 0..1
    const int rowbase = blockIdx.y * BM;
    const int colbase = blockIdx.x * BN;

    float acc[2][8][4];
#pragma unroll
    for (int i = 0; i < 2; i++)
#pragma unroll
        for (int j = 0; j < 8; j++)
#pragma unroll
            for (int q = 0; q < 4; q++) acc[i][j][q] = 0.f;

    const uint32_t sA = (uint32_t)__cvta_generic_to_shared(&As[0][0]);
    const uint32_t sB = (uint32_t)__cvta_generic_to_shared(&Bs[0][0]);

    const int ldr = tid >> 3;          // 0..31
    const int ldc = (tid & 7) * 8;     // half column (8 per uint4)

    const __half* gA = g_xa + (size_t)(rowbase) * KEXT;
    const __half* gB = g_xb + (size_t)(colbase) * KEXT;

    // prefetch chunk 0
    uint4 pa[4], pb[4];
#pragma unroll
    for (int p = 0; p < 4; p++) {
        int r = p * 32 + ldr;
        pa[p] = *(const uint4*)(gA + (size_t)r * KEXT + ldc);
        pb[p] = *(const uint4*)(gB + (size_t)r * KEXT + ldc);
    }

#pragma unroll 1
    for (int kc = 0; kc < KEXT / BK; kc++) {
#pragma unroll
        for (int p = 0; p < 4; p++) {
            int r = p * 32 + ldr;
            *(uint4*)&As[r][ldc] = pa[p];
            *(uint4*)&Bs[r][ldc] = pb[p];
        }
        __syncthreads();

        if (kc + 1 < KEXT / BK) {
            int koff = (kc + 1) * BK;
#pragma unroll
            for (int p = 0; p < 4; p++) {
                int r = p * 32 + ldr;
                pa[p] = *(const uint4*)(gA + (size_t)r * KEXT + koff + ldc);
                pb[p] = *(const uint4*)(gB + (size_t)r * KEXT + koff + ldc);
            }
        }

#pragma unroll
        for (int ks = 0; ks < 4; ks++) {
            uint32_t a[2][4];
#pragma unroll
            for (int mi = 0; mi < 2; mi++) {
                uint32_t addr = sA + (uint32_t)(((wm * 32 + mi * 16 + (lane & 15)) * SST
                                                 + ks * 16 + (lane >> 4) * 8) * 2);
                ldsm_x4(a[mi], addr);
            }
#pragma unroll
            for (int nj = 0; nj < 4; nj++) {
                uint32_t bb[4];
                uint32_t addr = sB + (uint32_t)(((wn * 64 + nj * 16 + (lane & 15)) * SST
                                                 + ks * 16 + (lane >> 4) * 8) * 2);
                ldsm_x4(bb, addr);
#pragma unroll
                for (int mi = 0; mi < 2; mi++) {
                    mma_f16(acc[mi][2 * nj + 0], a[mi], bb[0], bb[2]);
                    mma_f16(acc[mi][2 * nj + 1], a[mi], bb[1], bb[3]);
                }
            }
        }
        __syncthreads();
    }

    // epilogue: sim = -sqrt(max(x2+xn2-2*dot,0)) -> scratch, fused row min/max
#pragma unroll
    for (int mi = 0; mi < 2; mi++) {
        int r0 = rowbase + wm * 32 + mi * 16 + (lane >> 2);
        int r1 = r0 + 8;
        float xa = g_x2[r0];
        float xb = g_x2[r1];
        float mn0 = 3.4e38f, mx0 = -3.4e38f;
        float mn1 = 3.4e38f, mx1 = -3.4e38f;
#pragma unroll
        for (int nj8 = 0; nj8 < 8; nj8++) {
            int c0 = colbase + wn * 64 + nj8 * 8 + (lane & 3) * 2;
            float y0 = g_xn2[c0];
            float y1 = g_xn2[c0 + 1];
            float2 s0, s1;
            s0.x = -sqrtf(fmaxf(xa + y0 - 2.f * acc[mi][nj8][0], 0.f));
            s0.y = -sqrtf(fmaxf(xa + y1 - 2.f * acc[mi][nj8][1], 0.f));
            s1.x = -sqrtf(fmaxf(xb + y0 - 2.f * acc[mi][nj8][2], 0.f));
            s1.y = -sqrtf(fmaxf(xb + y1 - 2.f * acc[mi][nj8][3], 0.f));
            *(float2*)(g_sim + (size_t)r0 * M + c0) = s0;
            *(float2*)(g_sim + (size_t)r1 * M + c0) = s1;
            mn0 = fminf(mn0, fminf(s0.x, s0.y));
            mx0 = fmaxf(mx0, fmaxf(s0.x, s0.y));
            mn1 = fminf(mn1, fminf(s1.x, s1.y));
            mx1 = fmaxf(mx1, fmaxf(s1.x, s1.y));
        }
        // reduce across the 4 lanes (lane&3) that share each row
#pragma unroll
        for (int off = 1; off < 4; off <<= 1) {
            mn0 = fminf(mn0, __shfl_xor_sync(0xffffffffu, mn0, off));
            mx0 = fmaxf(mx0, __shfl_xor_sync(0xffffffffu, mx0, off));
            mn1 = fminf(mn1, __shfl_xor_sync(0xffffffffu, mn1, off));
            mx1 = fmaxf(mx1, __shfl_xor_sync(0xffffffffu, mx1, off));
        }
        if ((lane & 3) == 0) {
            atomicMin(&g_rminu[r0], fkey(mn0));
            atomicMax(&g_rmaxu[r0], fkey(mx0));
            atomicMin(&g_rminu[r1], fkey(mn1));
            atomicMax(&g_rmaxu[r1], fkey(mx1));
        }
    }
}

// ---------------- normalize + soft-KNN shift -------------------------------
__device__ __forceinline__ float sknn(float v, float mn, float inv,
                                      float k, float alpha) {
    float s = fmaxf((v - mn) * inv, EPSF);
    float sh = alpha * (k - s) * logf(s / k);
    return s + ((s <= k) ? sh : 0.f);
}

__global__ void epilogue_kernel(float* __restrict__ out, int M) {
    int row = blockIdx.y;
    int c = (blockIdx.x * blockDim.x + threadIdx.x) * 4;
    if (c >= M) return;
    float k  = g_k[row];
    float t  = g_t[row];
    float mn = funkey(g_rminu[row]);
    float mx = funkey(g_rmaxu[row]);
    float inv = 1.f / (mx - mn);
    float alpha = t / (1.f - t);
    float4 v = *(const float4*)(g_sim + (size_t)row * M + c);
    float4 o;
    o.x = sknn(v.x, mn, inv, k, alpha);
    o.y = sknn(v.y, mn, inv, k, alpha);
    o.z = sknn(v.z, mn, inv, k, alpha);
    o.w = sknn(v.w, mn, inv, k, alpha);
    *(float4*)(out + (size_t)row * M + c) = o;
}

// ---------------- launcher ---------------------------------------------------
extern "C" void kernel_launch(void* const* d_in, const int* in_sizes, int n_in,
                              void* d_out, int out_size) {
    const float* x  = (const float*)d_in[0];
    const float* xn = (const float*)d_in[1];
    const float* W  = (const float*)d_in[2];
    const float* b  = (const float*)d_in[3];
    float* out = (float*)d_out;

    int D = in_sizes[2] / 2;            // 256
    int N = in_sizes[0] / D;            // 8192
    int M = in_sizes[1] / D;            // 8192

    init_minmax_kernel<<<(N + 255) / 256, 256>>>(N);
    prep_x_kernel <<<(N + 7) / 8, 256>>>(x, W, b, N);
    prep_xn_kernel<<<(M + 7) / 8, 256>>>(xn, M);

    dim3 gg(M / BN, N / BM);
    gemm_sim_kernel<<<gg, 256>>>(M);

    dim3 ge((M / 4 + 255) / 256, N);
    epilogue_kernel<<<ge, 256>>>(out, M);
}

// round 9
// speedup vs baseline: 2.2019x; 1.1578x over previous
#include <cuda_runtime.h>
#include <cuda_fp16.h>
#include <cstdint>

#define NROWS 8192
#define D_FIX 256
#define KEXT  768             // 3 segments of 256: hh, hm, mh
#define EPSF  1e-12f

// ---------------- scratch (static device arrays; no runtime allocation) ----
__device__ float g_sim[(size_t)NROWS * (size_t)NROWS];          // 256 MB
__device__ __align__(16) __half g_xa[(size_t)NROWS * KEXT];     // 12.6 MB
__device__ __align__(16) __half g_xb[(size_t)NROWS * KEXT];     // 12.6 MB
__device__ float g_x2[NROWS], g_xn2[NROWS];
__device__ float g_k[NROWS], g_t[NROWS];
__device__ unsigned int g_rminu[NROWS], g_rmaxu[NROWS];

// monotone float<->uint key
__device__ __forceinline__ unsigned int fkey(float f) {
    unsigned int b = __float_as_uint(f);
    return (b & 0x80000000u) ? ~b : (b | 0x80000000u);
}
__device__ __forceinline__ float funkey(unsigned int u) {
    return __uint_as_float((u & 0x80000000u) ? (u & 0x7FFFFFFFu) : ~u);
}

__global__ void init_minmax_kernel(int N) {
    int i = blockIdx.x * blockDim.x + threadIdx.x;
    if (i < N) { g_rminu[i] = 0xFFFFFFFFu; g_rmaxu[i] = 0u; }
}

// ---------------- prep: fp16 2-way split + row norms + sigmoid head --------
// A segments: [h | h | m],  B segments: [h | m | h]
__global__ void prep_x_kernel(const float* __restrict__ x,
                              const float* __restrict__ W,
                              const float* __restrict__ b, int N) {
    int row  = blockIdx.x * 8 + (threadIdx.x >> 5);
    int lane = threadIdx.x & 31;
    if (row >= N) return;
    const float* xr = x + (size_t)row * D_FIX;
    float s2 = 0.f, p0 = 0.f, p1 = 0.f;
#pragma unroll
    for (int c = lane * 4; c < D_FIX; c += 128) {
        float4 v = *(const float4*)(xr + c);
        s2 += v.x * v.x + v.y * v.y + v.z * v.z + v.w * v.w;
        p0 += v.x * W[2*c + 0] + v.y * W[2*c + 2] + v.z * W[2*c + 4] + v.w * W[2*c + 6];
        p1 += v.x * W[2*c + 1] + v.y * W[2*c + 3] + v.z * W[2*c + 5] + v.w * W[2*c + 7];
        float f[4] = {v.x, v.y, v.z, v.w};
        size_t o = (size_t)row * KEXT + c;
#pragma unroll
        for (int q = 0; q < 4; q++) {
            __half h = __float2half_rn(f[q]);
            __half m = __float2half_rn(f[q] - __half2float(h));
            g_xa[o + q]       = h;
            g_xa[o + q + 256] = h;
            g_xa[o + q + 512] = m;
        }
    }
#pragma unroll
    for (int off = 16; off; off >>= 1) {
        s2 += __shfl_xor_sync(0xffffffffu, s2, off);
        p0 += __shfl_xor_sync(0xffffffffu, p0, off);
        p1 += __shfl_xor_sync(0xffffffffu, p1, off);
    }
    if (lane == 0) {
        g_x2[row] = s2;
        float kk = 1.f / (1.f + expf(-(p0 + b[0])));
        float tt = 1.f / (1.f + expf(-(p1 + b[1])));
        g_k[row] = fminf(fmaxf(kk, EPSF), 1.f - EPSF);
        g_t[row] = fminf(fmaxf(tt, EPSF), 1.f - EPSF);
    }
}

__global__ void prep_xn_kernel(const float* __restrict__ xn, int M) {
    int row  = blockIdx.x * 8 + (threadIdx.x >> 5);
    int lane = threadIdx.x & 31;
    if (row >= M) return;
    const float* xr = xn + (size_t)row * D_FIX;
    float s2 = 0.f;
#pragma unroll
    for (int c = lane * 4; c < D_FIX; c += 128) {
        float4 v = *(const float4*)(xr + c);
        s2 += v.x * v.x + v.y * v.y + v.z * v.z + v.w * v.w;
        float f[4] = {v.x, v.y, v.z, v.w};
        size_t o = (size_t)row * KEXT + c;
#pragma unroll
        for (int q = 0; q < 4; q++) {
            __half h = __float2half_rn(f[q]);
            __half m = __float2half_rn(f[q] - __half2float(h));
            g_xb[o + q]       = h;
            g_xb[o + q + 256] = m;
            g_xb[o + q + 512] = h;
        }
    }
#pragma unroll
    for (int off = 16; off; off >>= 1)
        s2 += __shfl_xor_sync(0xffffffffu, s2, off);
    if (lane == 0) g_xn2[row] = s2;
}

// ---------------- fp16 mma.sync GEMM + sim epilogue + fused min/max --------
// CTA tile 128x128, K=768 in 12 chunks of 64. 8 warps: 4(m) x 2(n),
// each warp 32x64 via mma.sync.m16n8k16 f16. Smem stride 72 halfs.
// 2 CTAs/SM (occupancy) hide load & barrier latency; no register prefetch.
#define BM 128
#define BN 128
#define BK 64
#define SST 72

__device__ __forceinline__ void ldsm_x4(uint32_t* r, uint32_t addr) {
    asm volatile("ldmatrix.sync.aligned.m8n8.x4.shared.b16 {%0,%1,%2,%3}, [%4];"
                 : "=r"(r[0]), "=r"(r[1]), "=r"(r[2]), "=r"(r[3]) : "r"(addr));
}

__device__ __forceinline__ void mma_f16(float* c, const uint32_t* a,
                                        uint32_t b0, uint32_t b1) {
    asm volatile(
        "mma.sync.aligned.m16n8k16.row.col.f32.f16.f16.f32 "
        "{%0,%1,%2,%3}, {%4,%5,%6,%7}, {%8,%9}, {%0,%1,%2,%3};"
        : "+f"(c[0]), "+f"(c[1]), "+f"(c[2]), "+f"(c[3])
        : "r"(a[0]), "r"(a[1]), "r"(a[2]), "r"(a[3]), "r"(b0), "r"(b1));
}

__global__ void __launch_bounds__(256, 2) gemm_sim_kernel(int M) {
    __shared__ __align__(16) __half As[BM][SST];
    __shared__ __align__(16) __half Bs[BN][SST];

    const int tid  = threadIdx.x;
    const int lane = tid & 31;
    const int warp = tid >> 5;
    const int wm   = warp >> 1;   // 0..3
    const int wn   = warp & 1;    // 0..1
    const int rowbase = blockIdx.y * BM;
    const int colbase = blockIdx.x * BN;

    float acc[2][8][4];
#pragma unroll
    for (int i = 0; i < 2; i++)
#pragma unroll
        for (int j = 0; j < 8; j++)
#pragma unroll
            for (int q = 0; q < 4; q++) acc[i][j][q] = 0.f;

    const uint32_t sA = (uint32_t)__cvta_generic_to_shared(&As[0][0]);
    const uint32_t sB = (uint32_t)__cvta_generic_to_shared(&Bs[0][0]);

    const int ldr = tid >> 3;          // 0..31
    const int ldc = (tid & 7) * 8;     // half column (8 per uint4)

    const __half* gA = g_xa + (size_t)(rowbase + ldr) * KEXT + ldc;
    const __half* gB = g_xb + (size_t)(colbase + ldr) * KEXT + ldc;

#pragma unroll 1
    for (int kc = 0; kc < KEXT / BK; kc++) {
        const int koff = kc * BK;
#pragma unroll
        for (int p = 0; p < 4; p++) {
            int r = p * 32 + ldr;
            *(uint4*)&As[r][ldc] = *(const uint4*)(gA + (size_t)(p * 32) * KEXT + koff);
            *(uint4*)&Bs[r][ldc] = *(const uint4*)(gB + (size_t)(p * 32) * KEXT + koff);
        }
        __syncthreads();

#pragma unroll
        for (int ks = 0; ks < 4; ks++) {
            uint32_t a[2][4];
#pragma unroll
            for (int mi = 0; mi < 2; mi++) {
                uint32_t addr = sA + (uint32_t)(((wm * 32 + mi * 16 + (lane & 15)) * SST
                                                 + ks * 16 + (lane >> 4) * 8) * 2);
                ldsm_x4(a[mi], addr);
            }
#pragma unroll
            for (int nj = 0; nj < 4; nj++) {
                uint32_t bb[4];
                uint32_t addr = sB + (uint32_t)(((wn * 64 + nj * 16 + (lane & 15)) * SST
                                                 + ks * 16 + (lane >> 4) * 8) * 2);
                ldsm_x4(bb, addr);
#pragma unroll
                for (int mi = 0; mi < 2; mi++) {
                    mma_f16(acc[mi][2 * nj + 0], a[mi], bb[0], bb[2]);
                    mma_f16(acc[mi][2 * nj + 1], a[mi], bb[1], bb[3]);
                }
            }
        }
        __syncthreads();
    }

    // epilogue: sim = -sqrt(max(x2+xn2-2*dot,0)) -> scratch, fused row min/max
#pragma unroll
    for (int mi = 0; mi < 2; mi++) {
        int r0 = rowbase + wm * 32 + mi * 16 + (lane >> 2);
        int r1 = r0 + 8;
        float xa = g_x2[r0];
        float xb = g_x2[r1];
        float mn0 = 3.4e38f, mx0 = -3.4e38f;
        float mn1 = 3.4e38f, mx1 = -3.4e38f;
#pragma unroll
        for (int nj8 = 0; nj8 < 8; nj8++) {
            int c0 = colbase + wn * 64 + nj8 * 8 + (lane & 3) * 2;
            float y0 = g_xn2[c0];
            float y1 = g_xn2[c0 + 1];
            float2 s0, s1;
            s0.x = -sqrtf(fmaxf(xa + y0 - 2.f * acc[mi][nj8][0], 0.f));
            s0.y = -sqrtf(fmaxf(xa + y1 - 2.f * acc[mi][nj8][1], 0.f));
            s1.x = -sqrtf(fmaxf(xb + y0 - 2.f * acc[mi][nj8][2], 0.f));
            s1.y = -sqrtf(fmaxf(xb + y1 - 2.f * acc[mi][nj8][3], 0.f));
            *(float2*)(g_sim + (size_t)r0 * M + c0) = s0;
            *(float2*)(g_sim + (size_t)r1 * M + c0) = s1;
            mn0 = fminf(mn0, fminf(s0.x, s0.y));
            mx0 = fmaxf(mx0, fmaxf(s0.x, s0.y));
            mn1 = fminf(mn1, fminf(s1.x, s1.y));
            mx1 = fmaxf(mx1, fmaxf(s1.x, s1.y));
        }
        // reduce across the 4 lanes (lane&3) that share each row
#pragma unroll
        for (int off = 1; off < 4; off <<= 1) {
            mn0 = fminf(mn0, __shfl_xor_sync(0xffffffffu, mn0, off));
            mx0 = fmaxf(mx0, __shfl_xor_sync(0xffffffffu, mx0, off));
            mn1 = fminf(mn1, __shfl_xor_sync(0xffffffffu, mn1, off));
            mx1 = fmaxf(mx1, __shfl_xor_sync(0xffffffffu, mx1, off));
        }
        if ((lane & 3) == 0) {
            atomicMin(&g_rminu[r0], fkey(mn0));
            atomicMax(&g_rmaxu[r0], fkey(mx0));
            atomicMin(&g_rminu[r1], fkey(mn1));
            atomicMax(&g_rmaxu[r1], fkey(mx1));
        }
    }
}

// ---------------- normalize + soft-KNN shift -------------------------------
__device__ __forceinline__ float sknn(float v, float mn, float inv,
                                      float k, float alpha) {
    float s = fmaxf((v - mn) * inv, EPSF);
    float sh = alpha * (k - s) * logf(s / k);
    return s + ((s <= k) ? sh : 0.f);
}

__global__ void epilogue_kernel(float* __restrict__ out, int M) {
    int row = blockIdx.y;
    int c = (blockIdx.x * blockDim.x + threadIdx.x) * 4;
    if (c >= M) return;
    float k  = g_k[row];
    float t  = g_t[row];
    float mn = funkey(g_rminu[row]);
    float mx = funkey(g_rmaxu[row]);
    float inv = 1.f / (mx - mn);
    float alpha = t / (1.f - t);
    float4 v = *(const float4*)(g_sim + (size_t)row * M + c);
    float4 o;
    o.x = sknn(v.x, mn, inv, k, alpha);
    o.y = sknn(v.y, mn, inv, k, alpha);
    o.z = sknn(v.z, mn, inv, k, alpha);
    o.w = sknn(v.w, mn, inv, k, alpha);
    *(float4*)(out + (size_t)row * M + c) = o;
}

// ---------------- launcher ---------------------------------------------------
extern "C" void kernel_launch(void* const* d_in, const int* in_sizes, int n_in,
                              void* d_out, int out_size) {
    const float* x  = (const float*)d_in[0];
    const float* xn = (const float*)d_in[1];
    const float* W  = (const float*)d_in[2];
    const float* b  = (const float*)d_in[3];
    float* out = (float*)d_out;

    int D = in_sizes[2] / 2;            // 256
    int N = in_sizes[0] / D;            // 8192
    int M = in_sizes[1] / D;            // 8192

    init_minmax_kernel<<<(N + 255) / 256, 256>>>(N);
    prep_x_kernel <<<(N + 7) / 8, 256>>>(x, W, b, N);
    prep_xn_kernel<<<(M + 7) / 8, 256>>>(xn, M);

    dim3 gg(M / BN, N / BM);
    gemm_sim_kernel<<<gg, 256>>>(M);

    dim3 ge((M / 4 + 255) / 256, N);
    epilogue_kernel<<<ge, 256>>>(out, M);
}

// round 10
// speedup vs baseline: 2.2447x; 1.0195x over previous
#include <cuda_runtime.h>
#include <cuda_fp16.h>
#include <cstdint>

#define NROWS 8192
#define D_FIX 256
#define KEXT  768             // 3 segments of 256: hh, hm, mh
#define EPSF  1e-12f

// ---------------- scratch (static device arrays; no runtime allocation) ----
__device__ float g_sim[(size_t)NROWS * (size_t)NROWS];          // 256 MB
__device__ __align__(16) __half g_xa[(size_t)NROWS * KEXT];     // 12.6 MB
__device__ __align__(16) __half g_xb[(size_t)NROWS * KEXT];     // 12.6 MB
__device__ float g_x2[NROWS], g_xn2[NROWS];
__device__ float g_k[NROWS], g_t[NROWS];
__device__ unsigned int g_rminu[NROWS], g_rmaxu[NROWS];

// monotone float<->uint key
__device__ __forceinline__ unsigned int fkey(float f) {
    unsigned int b = __float_as_uint(f);
    return (b & 0x80000000u) ? ~b : (b | 0x80000000u);
}
__device__ __forceinline__ float funkey(unsigned int u) {
    return __uint_as_float((u & 0x80000000u) ? (u & 0x7FFFFFFFu) : ~u);
}

__global__ void init_minmax_kernel(int N) {
    int i = blockIdx.x * blockDim.x + threadIdx.x;
    if (i < N) { g_rminu[i] = 0xFFFFFFFFu; g_rmaxu[i] = 0u; }
}

// ---------------- prep: fp16 2-way split + row norms + sigmoid head --------
// A segments: [h | h | m],  B segments: [h | m | h]
__global__ void prep_x_kernel(const float* __restrict__ x,
                              const float* __restrict__ W,
                              const float* __restrict__ b, int N) {
    int row  = blockIdx.x * 8 + (threadIdx.x >> 5);
    int lane = threadIdx.x & 31;
    if (row >= N) return;
    const float* xr = x + (size_t)row * D_FIX;
    float s2 = 0.f, p0 = 0.f, p1 = 0.f;
#pragma unroll
    for (int c = lane * 4; c < D_FIX; c += 128) {
        float4 v = *(const float4*)(xr + c);
        s2 += v.x * v.x + v.y * v.y + v.z * v.z + v.w * v.w;
        p0 += v.x * W[2*c + 0] + v.y * W[2*c + 2] + v.z * W[2*c + 4] + v.w * W[2*c + 6];
        p1 += v.x * W[2*c + 1] + v.y * W[2*c + 3] + v.z * W[2*c + 5] + v.w * W[2*c + 7];
        float f[4] = {v.x, v.y, v.z, v.w};
        size_t o = (size_t)row * KEXT + c;
#pragma unroll
        for (int q = 0; q < 4; q++) {
            __half h = __float2half_rn(f[q]);
            __half m = __float2half_rn(f[q] - __half2float(h));
            g_xa[o + q]       = h;
            g_xa[o + q + 256] = h;
            g_xa[o + q + 512] = m;
        }
    }
#pragma unroll
    for (int off = 16; off; off >>= 1) {
        s2 += __shfl_xor_sync(0xffffffffu, s2, off);
        p0 += __shfl_xor_sync(0xffffffffu, p0, off);
        p1 += __shfl_xor_sync(0xffffffffu, p1, off);
    }
    if (lane == 0) {
        g_x2[row] = s2;
        float kk = 1.f / (1.f + expf(-(p0 + b[0])));
        float tt = 1.f / (1.f + expf(-(p1 + b[1])));
        g_k[row] = fminf(fmaxf(kk, EPSF), 1.f - EPSF);
        g_t[row] = fminf(fmaxf(tt, EPSF), 1.f - EPSF);
    }
}

__global__ void prep_xn_kernel(const float* __restrict__ xn, int M) {
    int row  = blockIdx.x * 8 + (threadIdx.x >> 5);
    int lane = threadIdx.x & 31;
    if (row >= M) return;
    const float* xr = xn + (size_t)row * D_FIX;
    float s2 = 0.f;
#pragma unroll
    for (int c = lane * 4; c < D_FIX; c += 128) {
        float4 v = *(const float4*)(xr + c);
        s2 += v.x * v.x + v.y * v.y + v.z * v.z + v.w * v.w;
        float f[4] = {v.x, v.y, v.z, v.w};
        size_t o = (size_t)row * KEXT + c;
#pragma unroll
        for (int q = 0; q < 4; q++) {
            __half h = __float2half_rn(f[q]);
            __half m = __float2half_rn(f[q] - __half2float(h));
            g_xb[o + q]       = h;
            g_xb[o + q + 256] = m;
            g_xb[o + q + 512] = h;
        }
    }
#pragma unroll
    for (int off = 16; off; off >>= 1)
        s2 += __shfl_xor_sync(0xffffffffu, s2, off);
    if (lane == 0) g_xn2[row] = s2;
}

// ---------------- fp16 mma.sync GEMM, cp.async double-buffered --------------
// CTA tile 128x128, K=768 in 12 chunks of 64. 8 warps: 4(m) x 2(n),
// warp tile 32x64 via mma.sync.m16n8k16 f16. Smem stride 72 halfs.
// 2 CTAs/SM; global->smem via cp.async with 1-chunk-deep pipeline.
#define BM 128
#define BN 128
#define BK 64
#define SST 72
#define ATILE_B (BM * SST * 2)          // 18432 bytes per operand buffer
#define BUF_B   (2 * ATILE_B)           // A + B per stage = 36864
#define SMEM_TOT (2 * BUF_B)            // double buffered = 73728
#define NCH (KEXT / BK)                 // 12

__device__ __forceinline__ void ldsm_x4(uint32_t* r, uint32_t addr) {
    asm volatile("ldmatrix.sync.aligned.m8n8.x4.shared.b16 {%0,%1,%2,%3}, [%4];"
                 : "=r"(r[0]), "=r"(r[1]), "=r"(r[2]), "=r"(r[3]) : "r"(addr));
}

__device__ __forceinline__ void mma_f16(float* c, const uint32_t* a,
                                        uint32_t b0, uint32_t b1) {
    asm volatile(
        "mma.sync.aligned.m16n8k16.row.col.f32.f16.f16.f32 "
        "{%0,%1,%2,%3}, {%4,%5,%6,%7}, {%8,%9}, {%0,%1,%2,%3};"
        : "+f"(c[0]), "+f"(c[1]), "+f"(c[2]), "+f"(c[3])
        : "r"(a[0]), "r"(a[1]), "r"(a[2]), "r"(a[3]), "r"(b0), "r"(b1));
}

__device__ __forceinline__ void cp16(uint32_t dst, const void* src) {
    asm volatile("cp.async.cg.shared.global [%0], [%1], 16;"
                 :: "r"(dst), "l"(src) : "memory");
}
__device__ __forceinline__ void cp_commit() {
    asm volatile("cp.async.commit_group;" ::: "memory");
}
__device__ __forceinline__ void cp_wait1() {
    asm volatile("cp.async.wait_group 1;" ::: "memory");
}
__device__ __forceinline__ void cp_wait0() {
    asm volatile("cp.async.wait_group 0;" ::: "memory");
}

__global__ void __launch_bounds__(256, 2) gemm_sim_kernel(int M) {
    extern __shared__ __align__(16) char dsm[];
    const uint32_t sbase = (uint32_t)__cvta_generic_to_shared(dsm);

    const int tid  = threadIdx.x;
    const int lane = tid & 31;
    const int warp = tid >> 5;
    const int wm   = warp >> 1;   // 0..3
    const int wn   = warp & 1;    // 0..1
    const int rowbase = blockIdx.y * BM;
    const int colbase = blockIdx.x * BN;

    float acc[2][8][4];
#pragma unroll
    for (int i = 0; i < 2; i++)
#pragma unroll
        for (int j = 0; j < 8; j++)
#pragma unroll
            for (int q = 0; q < 4; q++) acc[i][j][q] = 0.f;

    const int ldr = tid >> 3;          // 0..31
    const int ldc = (tid & 7) * 8;     // half column (8 per uint4)

    const __half* gA = g_xa + (size_t)(rowbase + ldr) * KEXT + ldc;
    const __half* gB = g_xb + (size_t)(colbase + ldr) * KEXT + ldc;
    const uint32_t dA = sbase + (ldr * SST + ldc) * 2;             // + p*BUF_B
    const uint32_t dB = dA + ATILE_B;

    // issue chunk 0 into buffer 0
#pragma unroll
    for (int p = 0; p < 4; p++) {
        cp16(dA + p * 32 * SST * 2, gA + (size_t)(p * 32) * KEXT);
        cp16(dB + p * 32 * SST * 2, gB + (size_t)(p * 32) * KEXT);
    }
    cp_commit();

#pragma unroll 1
    for (int kc = 0; kc < NCH; kc++) {
        const uint32_t bufoff = (uint32_t)(kc & 1) * BUF_B;
        // issue next chunk into the other buffer
        if (kc + 1 < NCH) {
            const uint32_t nb = (uint32_t)((kc + 1) & 1) * BUF_B;
            const int koff = (kc + 1) * BK;
#pragma unroll
            for (int p = 0; p < 4; p++) {
                cp16(dA + nb + p * 32 * SST * 2, gA + (size_t)(p * 32) * KEXT + koff);
                cp16(dB + nb + p * 32 * SST * 2, gB + (size_t)(p * 32) * KEXT + koff);
            }
            cp_commit();
            cp_wait1();
        } else {
            cp_wait0();
        }
        __syncthreads();

        const uint32_t sA = sbase + bufoff;
        const uint32_t sB = sA + ATILE_B;
#pragma unroll
        for (int ks = 0; ks < 4; ks++) {
            uint32_t a[2][4];
#pragma unroll
            for (int mi = 0; mi < 2; mi++) {
                uint32_t addr = sA + (uint32_t)(((wm * 32 + mi * 16 + (lane & 15)) * SST
                                                 + ks * 16 + (lane >> 4) * 8) * 2);
                ldsm_x4(a[mi], addr);
            }
#pragma unroll
            for (int nj = 0; nj < 4; nj++) {
                uint32_t bb[4];
                uint32_t addr = sB + (uint32_t)(((wn * 64 + nj * 16 + (lane & 15)) * SST
                                                 + ks * 16 + (lane >> 4) * 8) * 2);
                ldsm_x4(bb, addr);
#pragma unroll
                for (int mi = 0; mi < 2; mi++) {
                    mma_f16(acc[mi][2 * nj + 0], a[mi], bb[0], bb[2]);
                    mma_f16(acc[mi][2 * nj + 1], a[mi], bb[1], bb[3]);
                }
            }
        }
        __syncthreads();
    }

    // epilogue: sim = -sqrt(max(x2+xn2-2*dot,0)) -> scratch, fused row min/max
#pragma unroll
    for (int mi = 0; mi < 2; mi++) {
        int r0 = rowbase + wm * 32 + mi * 16 + (lane >> 2);
        int r1 = r0 + 8;
        float xa = g_x2[r0];
        float xb = g_x2[r1];
        float mn0 = 3.4e38f, mx0 = -3.4e38f;
        float mn1 = 3.4e38f, mx1 = -3.4e38f;
#pragma unroll
        for (int nj8 = 0; nj8 < 8; nj8++) {
            int c0 = colbase + wn * 64 + nj8 * 8 + (lane & 3) * 2;
            float y0 = g_xn2[c0];
            float y1 = g_xn2[c0 + 1];
            float2 s0, s1;
            s0.x = -sqrtf(fmaxf(xa + y0 - 2.f * acc[mi][nj8][0], 0.f));
            s0.y = -sqrtf(fmaxf(xa + y1 - 2.f * acc[mi][nj8][1], 0.f));
            s1.x = -sqrtf(fmaxf(xb + y0 - 2.f * acc[mi][nj8][2], 0.f));
            s1.y = -sqrtf(fmaxf(xb + y1 - 2.f * acc[mi][nj8][3], 0.f));
            *(float2*)(g_sim + (size_t)r0 * M + c0) = s0;
            *(float2*)(g_sim + (size_t)r1 * M + c0) = s1;
            mn0 = fminf(mn0, fminf(s0.x, s0.y));
            mx0 = fmaxf(mx0, fmaxf(s0.x, s0.y));
            mn1 = fminf(mn1, fminf(s1.x, s1.y));
            mx1 = fmaxf(mx1, fmaxf(s1.x, s1.y));
        }
#pragma unroll
        for (int off = 1; off < 4; off <<= 1) {
            mn0 = fminf(mn0, __shfl_xor_sync(0xffffffffu, mn0, off));
            mx0 = fmaxf(mx0, __shfl_xor_sync(0xffffffffu, mx0, off));
            mn1 = fminf(mn1, __shfl_xor_sync(0xffffffffu, mn1, off));
            mx1 = fmaxf(mx1, __shfl_xor_sync(0xffffffffu, mx1, off));
        }
        if ((lane & 3) == 0) {
            atomicMin(&g_rminu[r0], fkey(mn0));
            atomicMax(&g_rmaxu[r0], fkey(mx0));
            atomicMin(&g_rminu[r1], fkey(mn1));
            atomicMax(&g_rmaxu[r1], fkey(mx1));
        }
    }
}

// ---------------- normalize + soft-KNN shift -------------------------------
__device__ __forceinline__ float sknn(float v, float mn, float inv,
                                      float k, float alpha) {
    float s = fmaxf((v - mn) * inv, EPSF);
    float sh = alpha * (k - s) * logf(s / k);
    return s + ((s <= k) ? sh : 0.f);
}

__global__ void epilogue_kernel(float* __restrict__ out, int M) {
    int row = blockIdx.y;
    int c = (blockIdx.x * blockDim.x + threadIdx.x) * 4;
    if (c >= M) return;
    float k  = g_k[row];
    float t  = g_t[row];
    float mn = funkey(g_rminu[row]);
    float mx = funkey(g_rmaxu[row]);
    float inv = 1.f / (mx - mn);
    float alpha = t / (1.f - t);
    float4 v = *(const float4*)(g_sim + (size_t)row * M + c);
    float4 o;
    o.x = sknn(v.x, mn, inv, k, alpha);
    o.y = sknn(v.y, mn, inv, k, alpha);
    o.z = sknn(v.z, mn, inv, k, alpha);
    o.w = sknn(v.w, mn, inv, k, alpha);
    *(float4*)(out + (size_t)row * M + c) = o;
}

// ---------------- launcher ---------------------------------------------------
extern "C" void kernel_launch(void* const* d_in, const int* in_sizes, int n_in,
                              void* d_out, int out_size) {
    const float* x  = (const float*)d_in[0];
    const float* xn = (const float*)d_in[1];
    const float* W  = (const float*)d_in[2];
    const float* b  = (const float*)d_in[3];
    float* out = (float*)d_out;

    int D = in_sizes[2] / 2;            // 256
    int N = in_sizes[0] / D;            // 8192
    int M = in_sizes[1] / D;            // 8192

    cudaFuncSetAttribute(gemm_sim_kernel,
                         cudaFuncAttributeMaxDynamicSharedMemorySize, SMEM_TOT);

    init_minmax_kernel<<<(N + 255) / 256, 256>>>(N);
    prep_x_kernel <<<(N + 7) / 8, 256>>>(x, W, b, N);
    prep_xn_kernel<<<(M + 7) / 8, 256>>>(xn, M);

    dim3 gg(M / BN, N / BM);
    gemm_sim_kernel<<<gg, 256, SMEM_TOT>>>(M);

    dim3 ge((M / 4 + 255) / 256, N);
    epilogue_kernel<<<ge, 256>>>(out, M);
}

// round 11
// speedup vs baseline: 2.3418x; 1.0433x over previous
#include <cuda_runtime.h>
#include <cuda_fp16.h>
#include <cstdint>

#define NROWS 8192
#define D_FIX 256
#define KEXT  768             // 3 segments of 256: hh, hm, mh
#define EPSF  1e-12f

// ---------------- scratch (static device arrays; no runtime allocation) ----
__device__ float g_sim[(size_t)NROWS * (size_t)NROWS];          // 256 MB
__device__ __align__(16) __half g_xa[(size_t)NROWS * KEXT];     // 12.6 MB
__device__ __align__(16) __half g_xb[(size_t)NROWS * KEXT];     // 12.6 MB
__device__ float g_x2[NROWS], g_xn2[NROWS];
__device__ float g_k[NROWS], g_t[NROWS];
__device__ unsigned int g_rminu[NROWS], g_rmaxu[NROWS];

// monotone float<->uint key
__device__ __forceinline__ unsigned int fkey(float f) {
    unsigned int b = __float_as_uint(f);
    return (b & 0x80000000u) ? ~b : (b | 0x80000000u);
}
__device__ __forceinline__ float funkey(unsigned int u) {
    return __uint_as_float((u & 0x80000000u) ? (u & 0x7FFFFFFFu) : ~u);
}

// ---------------- prep: fp16 2-way split + row norms + sigmoid head --------
// A segments: [h | h | m],  B segments: [h | m | h]
// Also initializes the per-row min/max atomic identities (no separate kernel).
__global__ void prep_x_kernel(const float* __restrict__ x,
                              const float* __restrict__ W,
                              const float* __restrict__ b, int N) {
    int row  = blockIdx.x * 8 + (threadIdx.x >> 5);
    int lane = threadIdx.x & 31;
    if (row >= N) return;
    const float* xr = x + (size_t)row * D_FIX;
    float s2 = 0.f, p0 = 0.f, p1 = 0.f;
#pragma unroll
    for (int c = lane * 4; c < D_FIX; c += 128) {
        float4 v = *(const float4*)(xr + c);
        s2 += v.x * v.x + v.y * v.y + v.z * v.z + v.w * v.w;
        p0 += v.x * W[2*c + 0] + v.y * W[2*c + 2] + v.z * W[2*c + 4] + v.w * W[2*c + 6];
        p1 += v.x * W[2*c + 1] + v.y * W[2*c + 3] + v.z * W[2*c + 5] + v.w * W[2*c + 7];
        float f[4] = {v.x, v.y, v.z, v.w};
        size_t o = (size_t)row * KEXT + c;
#pragma unroll
        for (int q = 0; q < 4; q++) {
            __half h = __float2half_rn(f[q]);
            __half m = __float2half_rn(f[q] - __half2float(h));
            g_xa[o + q]       = h;
            g_xa[o + q + 256] = h;
            g_xa[o + q + 512] = m;
        }
    }
#pragma unroll
    for (int off = 16; off; off >>= 1) {
        s2 += __shfl_xor_sync(0xffffffffu, s2, off);
        p0 += __shfl_xor_sync(0xffffffffu, p0, off);
        p1 += __shfl_xor_sync(0xffffffffu, p1, off);
    }
    if (lane == 0) {
        g_x2[row] = s2;
        float kk = 1.f / (1.f + expf(-(p0 + b[0])));
        float tt = 1.f / (1.f + expf(-(p1 + b[1])));
        g_k[row] = fminf(fmaxf(kk, EPSF), 1.f - EPSF);
        g_t[row] = fminf(fmaxf(tt, EPSF), 1.f - EPSF);
    }
    if (lane == 1) g_rminu[row] = 0xFFFFFFFFu;
    if (lane == 2) g_rmaxu[row] = 0u;
}

__global__ void prep_xn_kernel(const float* __restrict__ xn, int M) {
    int row  = blockIdx.x * 8 + (threadIdx.x >> 5);
    int lane = threadIdx.x & 31;
    if (row >= M) return;
    const float* xr = xn + (size_t)row * D_FIX;
    float s2 = 0.f;
#pragma unroll
    for (int c = lane * 4; c < D_FIX; c += 128) {
        float4 v = *(const float4*)(xr + c);
        s2 += v.x * v.x + v.y * v.y + v.z * v.z + v.w * v.w;
        float f[4] = {v.x, v.y, v.z, v.w};
        size_t o = (size_t)row * KEXT + c;
#pragma unroll
        for (int q = 0; q < 4; q++) {
            __half h = __float2half_rn(f[q]);
            __half m = __float2half_rn(f[q] - __half2float(h));
            g_xb[o + q]       = h;
            g_xb[o + q + 256] = m;
            g_xb[o + q + 512] = h;
        }
    }
#pragma unroll
    for (int off = 16; off; off >>= 1)
        s2 += __shfl_xor_sync(0xffffffffu, s2, off);
    if (lane == 0) g_xn2[row] = s2;
}

// ---------------- fp16 mma.sync GEMM, 3-stage cp.async pipeline -------------
// CTA tile 128x128, K=768 in 12 chunks of 64. 8 warps: 4(m) x 2(n),
// warp tile 32x64 via mma.sync.m16n8k16 f16. Smem stride 72 halfs.
// 2 CTAs/SM. All B fragments hoisted per ks-step (dependency-free mma block).
#define BM 128
#define BN 128
#define BK 64
#define SST 72
#define ATILE_B (BM * SST * 2)          // 18432 bytes per operand buffer
#define BUF_B   (2 * ATILE_B)           // A + B per stage = 36864
#define NSTAGE  3
#define SMEM_TOT (NSTAGE * BUF_B)       // 110592
#define NCH (KEXT / BK)                 // 12

__device__ __forceinline__ void ldsm_x4(uint32_t* r, uint32_t addr) {
    asm volatile("ldmatrix.sync.aligned.m8n8.x4.shared.b16 {%0,%1,%2,%3}, [%4];"
                 : "=r"(r[0]), "=r"(r[1]), "=r"(r[2]), "=r"(r[3]) : "r"(addr));
}

__device__ __forceinline__ void mma_f16(float* c, const uint32_t* a,
                                        uint32_t b0, uint32_t b1) {
    asm volatile(
        "mma.sync.aligned.m16n8k16.row.col.f32.f16.f16.f32 "
        "{%0,%1,%2,%3}, {%4,%5,%6,%7}, {%8,%9}, {%0,%1,%2,%3};"
        : "+f"(c[0]), "+f"(c[1]), "+f"(c[2]), "+f"(c[3])
        : "r"(a[0]), "r"(a[1]), "r"(a[2]), "r"(a[3]), "r"(b0), "r"(b1));
}

__device__ __forceinline__ void cp16(uint32_t dst, const void* src) {
    asm volatile("cp.async.cg.shared.global [%0], [%1], 16;"
                 :: "r"(dst), "l"(src) : "memory");
}
__device__ __forceinline__ void cp_commit() {
    asm volatile("cp.async.commit_group;" ::: "memory");
}
template <int Nw>
__device__ __forceinline__ void cp_wait() {
    asm volatile("cp.async.wait_group %0;" :: "n"(Nw) : "memory");
}

__global__ void __launch_bounds__(256, 2) gemm_sim_kernel(int M) {
    extern __shared__ __align__(16) char dsm[];
    const uint32_t sbase = (uint32_t)__cvta_generic_to_shared(dsm);

    const int tid  = threadIdx.x;
    const int lane = tid & 31;
    const int warp = tid >> 5;
    const int wm   = warp >> 1;   // 0..3
    const int wn   = warp & 1;    // 0..1
    const int rowbase = blockIdx.y * BM;
    const int colbase = blockIdx.x * BN;

    float acc[2][8][4];
#pragma unroll
    for (int i = 0; i < 2; i++)
#pragma unroll
        for (int j = 0; j < 8; j++)
#pragma unroll
            for (int q = 0; q < 4; q++) acc[i][j][q] = 0.f;

    const int ldr = tid >> 3;          // 0..31
    const int ldc = (tid & 7) * 8;     // half column (8 per uint4)

    const __half* gA = g_xa + (size_t)(rowbase + ldr) * KEXT + ldc;
    const __half* gB = g_xb + (size_t)(colbase + ldr) * KEXT + ldc;
    const uint32_t dA = sbase + (ldr * SST + ldc) * 2;             // + stage*BUF_B
    const uint32_t dB = dA + ATILE_B;

    // per-warp smem ldsm bases (stage offset added in loop)
    const uint32_t aAddr0 = sbase + (uint32_t)(((wm * 32 + (lane & 15)) * SST
                                                + (lane >> 4) * 8) * 2);
    const uint32_t bAddr0 = sbase + ATILE_B
                          + (uint32_t)(((wn * 64 + (lane & 15)) * SST
                                        + (lane >> 4) * 8) * 2);

    // prologue: issue chunks 0 and 1
#pragma unroll
    for (int s = 0; s < 2; s++) {
        const uint32_t so = (uint32_t)s * BUF_B;
#pragma unroll
        for (int p = 0; p < 4; p++) {
            cp16(dA + so + p * 32 * SST * 2, gA + (size_t)(p * 32) * KEXT + s * BK);
            cp16(dB + so + p * 32 * SST * 2, gB + (size_t)(p * 32) * KEXT + s * BK);
        }
        cp_commit();
    }

#pragma unroll 1
    for (int kc = 0; kc < NCH; kc++) {
        const uint32_t so = (uint32_t)(kc % NSTAGE) * BUF_B;
        if (kc + 2 < NCH) {
            const uint32_t ns = (uint32_t)((kc + 2) % NSTAGE) * BUF_B;
            const int koff = (kc + 2) * BK;
#pragma unroll
            for (int p = 0; p < 4; p++) {
                cp16(dA + ns + p * 32 * SST * 2, gA + (size_t)(p * 32) * KEXT + koff);
                cp16(dB + ns + p * 32 * SST * 2, gB + (size_t)(p * 32) * KEXT + koff);
            }
            cp_commit();
            cp_wait<2>();
        } else if (kc + 1 < NCH) {
            cp_wait<1>();
        } else {
            cp_wait<0>();
        }
        __syncthreads();

#pragma unroll
        for (int ks = 0; ks < 4; ks++) {
            uint32_t a[2][4], bb[4][4];
            const uint32_t ak = aAddr0 + so + ks * 32;   // ks*16 halfs
            const uint32_t bk = bAddr0 + so + ks * 32;
            ldsm_x4(a[0], ak);
            ldsm_x4(a[1], ak + (uint32_t)(16 * SST * 2));
#pragma unroll
            for (int nj = 0; nj < 4; nj++)
                ldsm_x4(bb[nj], bk + (uint32_t)(nj * 16 * SST * 2));
#pragma unroll
            for (int nj = 0; nj < 4; nj++) {
#pragma unroll
                for (int mi = 0; mi < 2; mi++) {
                    mma_f16(acc[mi][2 * nj + 0], a[mi], bb[nj][0], bb[nj][2]);
                    mma_f16(acc[mi][2 * nj + 1], a[mi], bb[nj][1], bb[nj][3]);
                }
            }
        }
        __syncthreads();
    }

    // epilogue: sim = -sqrt(max(x2+xn2-2*dot,0)) -> scratch, fused row min/max
#pragma unroll
    for (int mi = 0; mi < 2; mi++) {
        int r0 = rowbase + wm * 32 + mi * 16 + (lane >> 2);
        int r1 = r0 + 8;
        float xa = g_x2[r0];
        float xb = g_x2[r1];
        float mn0 = 3.4e38f, mx0 = -3.4e38f;
        float mn1 = 3.4e38f, mx1 = -3.4e38f;
#pragma unroll
        for (int nj8 = 0; nj8 < 8; nj8++) {
            int c0 = colbase + wn * 64 + nj8 * 8 + (lane & 3) * 2;
            float y0 = g_xn2[c0];
            float y1 = g_xn2[c0 + 1];
            float2 s0, s1;
            s0.x = -sqrtf(fmaxf(xa + y0 - 2.f * acc[mi][nj8][0], 0.f));
            s0.y = -sqrtf(fmaxf(xa + y1 - 2.f * acc[mi][nj8][1], 0.f));
            s1.x = -sqrtf(fmaxf(xb + y0 - 2.f * acc[mi][nj8][2], 0.f));
            s1.y = -sqrtf(fmaxf(xb + y1 - 2.f * acc[mi][nj8][3], 0.f));
            *(float2*)(g_sim + (size_t)r0 * M + c0) = s0;
            *(float2*)(g_sim + (size_t)r1 * M + c0) = s1;
            mn0 = fminf(mn0, fminf(s0.x, s0.y));
            mx0 = fmaxf(mx0, fmaxf(s0.x, s0.y));
            mn1 = fminf(mn1, fminf(s1.x, s1.y));
            mx1 = fmaxf(mx1, fmaxf(s1.x, s1.y));
        }
#pragma unroll
        for (int off = 1; off < 4; off <<= 1) {
            mn0 = fminf(mn0, __shfl_xor_sync(0xffffffffu, mn0, off));
            mx0 = fmaxf(mx0, __shfl_xor_sync(0xffffffffu, mx0, off));
            mn1 = fminf(mn1, __shfl_xor_sync(0xffffffffu, mn1, off));
            mx1 = fmaxf(mx1, __shfl_xor_sync(0xffffffffu, mx1, off));
        }
        if ((lane & 3) == 0) {
            atomicMin(&g_rminu[r0], fkey(mn0));
            atomicMax(&g_rmaxu[r0], fkey(mx0));
            atomicMin(&g_rminu[r1], fkey(mn1));
            atomicMax(&g_rmaxu[r1], fkey(mx1));
        }
    }
}

// ---------------- normalize + soft-KNN shift -------------------------------
// shift = alpha*(k-s)*(log(s)-log(k)) : one LG2 per element, no divide.
__global__ void epilogue_kernel(float* __restrict__ out, int M) {
    int row = blockIdx.y;
    int c = (blockIdx.x * blockDim.x + threadIdx.x) * 4;
    if (c >= M) return;
    float k    = g_k[row];
    float t    = g_t[row];
    float mn   = funkey(g_rminu[row]);
    float mx   = funkey(g_rmaxu[row]);
    float inv  = 1.f / (mx - mn);
    float alpha = t / (1.f - t);
    float logk = __logf(k);
    float4 v = *(const float4*)(g_sim + (size_t)row * M + c);
    float4 o;
    {
        float s = fmaxf((v.x - mn) * inv, EPSF);
        o.x = s + ((s <= k) ? alpha * (k - s) * (__logf(s) - logk) : 0.f);
        s = fmaxf((v.y - mn) * inv, EPSF);
        o.y = s + ((s <= k) ? alpha * (k - s) * (__logf(s) - logk) : 0.f);
        s = fmaxf((v.z - mn) * inv, EPSF);
        o.z = s + ((s <= k) ? alpha * (k - s) * (__logf(s) - logk) : 0.f);
        s = fmaxf((v.w - mn) * inv, EPSF);
        o.w = s + ((s <= k) ? alpha * (k - s) * (__logf(s) - logk) : 0.f);
    }
    *(float4*)(out + (size_t)row * M + c) = o;
}

// ---------------- launcher ---------------------------------------------------
extern "C" void kernel_launch(void* const* d_in, const int* in_sizes, int n_in,
                              void* d_out, int out_size) {
    const float* x  = (const float*)d_in[0];
    const float* xn = (const float*)d_in[1];
    const float* W  = (const float*)d_in[2];
    const float* b  = (const float*)d_in[3];
    float* out = (float*)d_out;

    int D = in_sizes[2] / 2;            // 256
    int N = in_sizes[0] / D;            // 8192
    int M = in_sizes[1] / D;            // 8192

    cudaFuncSetAttribute(gemm_sim_kernel,
                         cudaFuncAttributeMaxDynamicSharedMemorySize, SMEM_TOT);

    prep_x_kernel <<<(N + 7) / 8, 256>>>(x, W, b, N);
    prep_xn_kernel<<<(M + 7) / 8, 256>>>(xn, M);

    dim3 gg(M / BN, N / BM);
    gemm_sim_kernel<<<gg, 256, SMEM_TOT>>>(M);

    dim3 ge((M / 4 + 255) / 256, N);
    epilogue_kernel<<<ge, 256>>>(out, M);
}

// round 12
// speedup vs baseline: 2.4951x; 1.0654x over previous
#include <cuda_runtime.h>
#include <cuda_fp16.h>
#include <cstdint>

#define NROWS 8192
#define D_FIX 256
#define KEXT  768             // 3 segments of 256: hh, hm, mh
#define EPSF  1e-12f

// ---------------- scratch (static device arrays; no runtime allocation) ----
__device__ float g_sim[(size_t)NROWS * (size_t)NROWS];          // 256 MB
__device__ __align__(16) __half g_xa[(size_t)NROWS * KEXT];     // 12.6 MB
__device__ __align__(16) __half g_xb[(size_t)NROWS * KEXT];     // 12.6 MB
__device__ float g_x2[NROWS], g_xn2[NROWS];
__device__ float g_k[NROWS], g_t[NROWS];
__device__ unsigned int g_rminu[NROWS], g_rmaxu[NROWS];

// monotone float<->uint key
__device__ __forceinline__ unsigned int fkey(float f) {
    unsigned int b = __float_as_uint(f);
    return (b & 0x80000000u) ? ~b : (b | 0x80000000u);
}
__device__ __forceinline__ float funkey(unsigned int u) {
    return __uint_as_float((u & 0x80000000u) ? (u & 0x7FFFFFFFu) : ~u);
}

// ---------------- prep: fp16 2-way split + row norms + sigmoid head --------
// A segments: [h | h | m],  B segments: [h | m | h]
// Also initializes the per-row min/max atomic identities.
__global__ void prep_x_kernel(const float* __restrict__ x,
                              const float* __restrict__ W,
                              const float* __restrict__ b, int N) {
    int row  = blockIdx.x * 8 + (threadIdx.x >> 5);
    int lane = threadIdx.x & 31;
    if (row >= N) return;
    const float* xr = x + (size_t)row * D_FIX;
    float s2 = 0.f, p0 = 0.f, p1 = 0.f;
#pragma unroll
    for (int c = lane * 4; c < D_FIX; c += 128) {
        float4 v = *(const float4*)(xr + c);
        s2 += v.x * v.x + v.y * v.y + v.z * v.z + v.w * v.w;
        p0 += v.x * W[2*c + 0] + v.y * W[2*c + 2] + v.z * W[2*c + 4] + v.w * W[2*c + 6];
        p1 += v.x * W[2*c + 1] + v.y * W[2*c + 3] + v.z * W[2*c + 5] + v.w * W[2*c + 7];
        float f[4] = {v.x, v.y, v.z, v.w};
        size_t o = (size_t)row * KEXT + c;
#pragma unroll
        for (int q = 0; q < 4; q++) {
            __half h = __float2half_rn(f[q]);
            __half m = __float2half_rn(f[q] - __half2float(h));
            g_xa[o + q]       = h;
            g_xa[o + q + 256] = h;
            g_xa[o + q + 512] = m;
        }
    }
#pragma unroll
    for (int off = 16; off; off >>= 1) {
        s2 += __shfl_xor_sync(0xffffffffu, s2, off);
        p0 += __shfl_xor_sync(0xffffffffu, p0, off);
        p1 += __shfl_xor_sync(0xffffffffu, p1, off);
    }
    if (lane == 0) {
        g_x2[row] = s2;
        float kk = 1.f / (1.f + expf(-(p0 + b[0])));
        float tt = 1.f / (1.f + expf(-(p1 + b[1])));
        g_k[row] = fminf(fmaxf(kk, EPSF), 1.f - EPSF);
        g_t[row] = fminf(fmaxf(tt, EPSF), 1.f - EPSF);
    }
    if (lane == 1) g_rminu[row] = 0xFFFFFFFFu;
    if (lane == 2) g_rmaxu[row] = 0u;
}

__global__ void prep_xn_kernel(const float* __restrict__ xn, int M) {
    int row  = blockIdx.x * 8 + (threadIdx.x >> 5);
    int lane = threadIdx.x & 31;
    if (row >= M) return;
    const float* xr = xn + (size_t)row * D_FIX;
    float s2 = 0.f;
#pragma unroll
    for (int c = lane * 4; c < D_FIX; c += 128) {
        float4 v = *(const float4*)(xr + c);
        s2 += v.x * v.x + v.y * v.y + v.z * v.z + v.w * v.w;
        float f[4] = {v.x, v.y, v.z, v.w};
        size_t o = (size_t)row * KEXT + c;
#pragma unroll
        for (int q = 0; q < 4; q++) {
            __half h = __float2half_rn(f[q]);
            __half m = __float2half_rn(f[q] - __half2float(h));
            g_xb[o + q]       = h;
            g_xb[o + q + 256] = m;
            g_xb[o + q + 512] = h;
        }
    }
#pragma unroll
    for (int off = 16; off; off >>= 1)
        s2 += __shfl_xor_sync(0xffffffffu, s2, off);
    if (lane == 0) g_xn2[row] = s2;
}

// ---------------- fp16 mma.sync GEMM, 3-stage pipeline, 1 barrier/chunk -----
#define BM 128
#define BN 128
#define BK 64
#define SST 72
#define ATILE_B (BM * SST * 2)          // 18432 bytes per operand buffer
#define BUF_B   (2 * ATILE_B)           // A + B per stage = 36864
#define NSTAGE  3
#define SMEM_TOT (NSTAGE * BUF_B)       // 110592
#define NCH (KEXT / BK)                 // 12

__device__ __forceinline__ void ldsm_x4(uint32_t* r, uint32_t addr) {
    asm volatile("ldmatrix.sync.aligned.m8n8.x4.shared.b16 {%0,%1,%2,%3}, [%4];"
                 : "=r"(r[0]), "=r"(r[1]), "=r"(r[2]), "=r"(r[3]) : "r"(addr));
}

__device__ __forceinline__ void mma_f16(float* c, const uint32_t* a,
                                        uint32_t b0, uint32_t b1) {
    asm volatile(
        "mma.sync.aligned.m16n8k16.row.col.f32.f16.f16.f32 "
        "{%0,%1,%2,%3}, {%4,%5,%6,%7}, {%8,%9}, {%0,%1,%2,%3};"
        : "+f"(c[0]), "+f"(c[1]), "+f"(c[2]), "+f"(c[3])
        : "r"(a[0]), "r"(a[1]), "r"(a[2]), "r"(a[3]), "r"(b0), "r"(b1));
}

__device__ __forceinline__ void cp16(uint32_t dst, const void* src) {
    asm volatile("cp.async.cg.shared.global [%0], [%1], 16;"
                 :: "r"(dst), "l"(src) : "memory");
}
__device__ __forceinline__ void cp_commit() {
    asm volatile("cp.async.commit_group;" ::: "memory");
}
template <int Nw>
__device__ __forceinline__ void cp_wait() {
    asm volatile("cp.async.wait_group %0;" :: "n"(Nw) : "memory");
}

__global__ void __launch_bounds__(256, 2) gemm_sim_kernel(int M) {
    extern __shared__ __align__(16) char dsm[];
    const uint32_t sbase = (uint32_t)__cvta_generic_to_shared(dsm);

    const int tid  = threadIdx.x;
    const int lane = tid & 31;
    const int warp = tid >> 5;
    const int wm   = warp >> 1;   // 0..3
    const int wn   = warp & 1;    // 0..1
    const int rowbase = blockIdx.y * BM;
    const int colbase = blockIdx.x * BN;

    float acc[2][8][4];
#pragma unroll
    for (int i = 0; i < 2; i++)
#pragma unroll
        for (int j = 0; j < 8; j++)
#pragma unroll
            for (int q = 0; q < 4; q++) acc[i][j][q] = 0.f;

    const int ldr = tid >> 3;          // 0..31
    const int ldc = (tid & 7) * 8;     // half column (8 per uint4)

    const __half* gA = g_xa + (size_t)(rowbase + ldr) * KEXT + ldc;
    const __half* gB = g_xb + (size_t)(colbase + ldr) * KEXT + ldc;
    const uint32_t dA = sbase + (ldr * SST + ldc) * 2;             // + stage*BUF_B
    const uint32_t dB = dA + ATILE_B;

    const uint32_t aAddr0 = sbase + (uint32_t)(((wm * 32 + (lane & 15)) * SST
                                                + (lane >> 4) * 8) * 2);
    const uint32_t bAddr0 = sbase + ATILE_B
                          + (uint32_t)(((wn * 64 + (lane & 15)) * SST
                                        + (lane >> 4) * 8) * 2);

    // prologue: issue chunks 0 and 1
#pragma unroll
    for (int s = 0; s < 2; s++) {
        const uint32_t so = (uint32_t)s * BUF_B;
#pragma unroll
        for (int p = 0; p < 4; p++) {
            cp16(dA + so + p * 32 * SST * 2, gA + (size_t)(p * 32) * KEXT + s * BK);
            cp16(dB + so + p * 32 * SST * 2, gB + (size_t)(p * 32) * KEXT + s * BK);
        }
        cp_commit();
    }

    // single barrier per chunk: at barrier(kc), all warps finished compute
    // kc-1, the only reader of stage (kc+2)%3 == (kc-1)%3 -> safe to prefetch.
#pragma unroll 1
    for (int kc = 0; kc < NCH; kc++) {
        const uint32_t so = (uint32_t)(kc % NSTAGE) * BUF_B;
        if (kc + 1 < NCH) cp_wait<1>(); else cp_wait<0>();
        __syncthreads();

        if (kc + 2 < NCH) {
            const uint32_t ns = (uint32_t)((kc + 2) % NSTAGE) * BUF_B;
            const int koff = (kc + 2) * BK;
#pragma unroll
            for (int p = 0; p < 4; p++) {
                cp16(dA + ns + p * 32 * SST * 2, gA + (size_t)(p * 32) * KEXT + koff);
                cp16(dB + ns + p * 32 * SST * 2, gB + (size_t)(p * 32) * KEXT + koff);
            }
            cp_commit();
        }

#pragma unroll
        for (int ks = 0; ks < 4; ks++) {
            uint32_t a[2][4], bb[4][4];
            const uint32_t ak = aAddr0 + so + ks * 32;   // ks*16 halfs
            const uint32_t bk = bAddr0 + so + ks * 32;
            ldsm_x4(a[0], ak);
            ldsm_x4(a[1], ak + (uint32_t)(16 * SST * 2));
#pragma unroll
            for (int nj = 0; nj < 4; nj++)
                ldsm_x4(bb[nj], bk + (uint32_t)(nj * 16 * SST * 2));
#pragma unroll
            for (int nj = 0; nj < 4; nj++) {
#pragma unroll
                for (int mi = 0; mi < 2; mi++) {
                    mma_f16(acc[mi][2 * nj + 0], a[mi], bb[nj][0], bb[nj][2]);
                    mma_f16(acc[mi][2 * nj + 1], a[mi], bb[nj][1], bb[nj][3]);
                }
            }
        }
    }

    // epilogue: sim = -sqrt(max(x2+xn2-2*dot,0)) -> scratch, fused row min/max
#pragma unroll
    for (int mi = 0; mi < 2; mi++) {
        int r0 = rowbase + wm * 32 + mi * 16 + (lane >> 2);
        int r1 = r0 + 8;
        float xa = g_x2[r0];
        float xb = g_x2[r1];
        float mn0 = 3.4e38f, mx0 = -3.4e38f;
        float mn1 = 3.4e38f, mx1 = -3.4e38f;
#pragma unroll
        for (int nj8 = 0; nj8 < 8; nj8++) {
            int c0 = colbase + wn * 64 + nj8 * 8 + (lane & 3) * 2;
            float y0 = g_xn2[c0];
            float y1 = g_xn2[c0 + 1];
            float2 s0, s1;
            s0.x = -sqrtf(fmaxf(xa + y0 - 2.f * acc[mi][nj8][0], 0.f));
            s0.y = -sqrtf(fmaxf(xa + y1 - 2.f * acc[mi][nj8][1], 0.f));
            s1.x = -sqrtf(fmaxf(xb + y0 - 2.f * acc[mi][nj8][2], 0.f));
            s1.y = -sqrtf(fmaxf(xb + y1 - 2.f * acc[mi][nj8][3], 0.f));
            *(float2*)(g_sim + (size_t)r0 * M + c0) = s0;
            *(float2*)(g_sim + (size_t)r1 * M + c0) = s1;
            mn0 = fminf(mn0, fminf(s0.x, s0.y));
            mx0 = fmaxf(mx0, fmaxf(s0.x, s0.y));
            mn1 = fminf(mn1, fminf(s1.x, s1.y));
            mx1 = fmaxf(mx1, fmaxf(s1.x, s1.y));
        }
#pragma unroll
        for (int off = 1; off < 4; off <<= 1) {
            mn0 = fminf(mn0, __shfl_xor_sync(0xffffffffu, mn0, off));
            mx0 = fmaxf(mx0, __shfl_xor_sync(0xffffffffu, mx0, off));
            mn1 = fminf(mn1, __shfl_xor_sync(0xffffffffu, mn1, off));
            mx1 = fmaxf(mx1, __shfl_xor_sync(0xffffffffu, mx1, off));
        }
        if ((lane & 3) == 0) {
            atomicMin(&g_rminu[r0], fkey(mn0));
            atomicMax(&g_rmaxu[r0], fkey(mx0));
            atomicMin(&g_rminu[r1], fkey(mn1));
            atomicMax(&g_rmaxu[r1], fkey(mx1));
        }
    }
}

// ---------------- normalize + soft-KNN shift (8 elems/thread) ---------------
__device__ __forceinline__ float sknn_fast(float v, float mn, float inv,
                                           float k, float alpha, float logk) {
    float s = fmaxf((v - mn) * inv, EPSF);
    return s + ((s <= k) ? alpha * (k - s) * (__logf(s) - logk) : 0.f);
}

__global__ void epilogue_kernel(float* __restrict__ out, int M) {
    int row = blockIdx.y;
    int c = (blockIdx.x * blockDim.x + threadIdx.x) * 8;
    if (c >= M) return;
    float k    = g_k[row];
    float t    = g_t[row];
    float mn   = funkey(g_rminu[row]);
    float mx   = funkey(g_rmaxu[row]);
    float inv  = 1.f / (mx - mn);
    float alpha = t / (1.f - t);
    float logk = __logf(k);
    const float* src = g_sim + (size_t)row * M + c;
    float4 v0 = *(const float4*)(src);
    float4 v1 = *(const float4*)(src + 4);
    float4 o0, o1;
    o0.x = sknn_fast(v0.x, mn, inv, k, alpha, logk);
    o0.y = sknn_fast(v0.y, mn, inv, k, alpha, logk);
    o0.z = sknn_fast(v0.z, mn, inv, k, alpha, logk);
    o0.w = sknn_fast(v0.w, mn, inv, k, alpha, logk);
    o1.x = sknn_fast(v1.x, mn, inv, k, alpha, logk);
    o1.y = sknn_fast(v1.y, mn, inv, k, alpha, logk);
    o1.z = sknn_fast(v1.z, mn, inv, k, alpha, logk);
    o1.w = sknn_fast(v1.w, mn, inv, k, alpha, logk);
    float* dst = out + (size_t)row * M + c;
    *(float4*)(dst)     = o0;
    *(float4*)(dst + 4) = o1;
}

// ---------------- launcher ---------------------------------------------------
extern "C" void kernel_launch(void* const* d_in, const int* in_sizes, int n_in,
                              void* d_out, int out_size) {
    const float* x  = (const float*)d_in[0];
    const float* xn = (const float*)d_in[1];
    const float* W  = (const float*)d_in[2];
    const float* b  = (const float*)d_in[3];
    float* out = (float*)d_out;

    int D = in_sizes[2] / 2;            // 256
    int N = in_sizes[0] / D;            // 8192
    int M = in_sizes[1] / D;            // 8192

    cudaFuncSetAttribute(gemm_sim_kernel,
                         cudaFuncAttributeMaxDynamicSharedMemorySize, SMEM_TOT);

    prep_x_kernel <<<(N + 7) / 8, 256>>>(x, W, b, N);
    prep_xn_kernel<<<(M + 7) / 8, 256>>>(xn, M);

    dim3 gg(M / BN, N / BM);
    gemm_sim_kernel<<<gg, 256, SMEM_TOT>>>(M);

    dim3 ge((M / 8 + 255) / 256, N);
    epilogue_kernel<<<ge, 256>>>(out, M);
}